// round 2
// baseline (speedup 1.0000x reference)
#include <cuda_runtime.h>
#include <math.h>

#define BB 8
#define TT 1024
#define CC 64

// Scratch (no allocation allowed in kernel_launch)
__device__ float g_q[BB*TT*CC];
__device__ float g_k[BB*TT*CC];
__device__ float g_v[BB*TT*CC];
__device__ float g_y[BB*TT*CC];

// ---------------------------------------------------------------------------
// Kernel 1: qkv = x @ Wqkv^T + bqkv, split into g_q/g_k/g_v
// grid = 128 blocks (64 rows each), block = 256 threads (16x16), 4x4 microtile
// ---------------------------------------------------------------------------
__global__ __launch_bounds__(256) void qkv_kernel(
    const float* __restrict__ x, const float* __restrict__ W,
    const float* __restrict__ bias)
{
    __shared__ float Xs[64][65];
    __shared__ float Ws[64][65];
    const int row0 = blockIdx.x * 64;
    const int tid = threadIdx.x;
    const int tx = tid & 15, ty = tid >> 4;
    const int i0 = ty * 4, j0 = tx * 4;

    // load X tile (64x64) as float4
    for (int k = tid; k < 64 * 16; k += 256) {
        int r = k >> 4, c4 = k & 15;
        float4 v = reinterpret_cast<const float4*>(x + (size_t)(row0 + r) * CC)[c4];
        Xs[r][c4 * 4 + 0] = v.x; Xs[r][c4 * 4 + 1] = v.y;
        Xs[r][c4 * 4 + 2] = v.z; Xs[r][c4 * 4 + 3] = v.w;
    }

    for (int chunk = 0; chunk < 3; ++chunk) {
        __syncthreads();
        for (int k = tid; k < 64 * 16; k += 256) {
            int r = k >> 4, c4 = k & 15;
            float4 v = reinterpret_cast<const float4*>(W + (size_t)(chunk * 64 + r) * CC)[c4];
            Ws[r][c4 * 4 + 0] = v.x; Ws[r][c4 * 4 + 1] = v.y;
            Ws[r][c4 * 4 + 2] = v.z; Ws[r][c4 * 4 + 3] = v.w;
        }
        __syncthreads();

        float acc[4][4] = {};
        #pragma unroll
        for (int c = 0; c < 64; ++c) {
            float xr[4], wr[4];
            #pragma unroll
            for (int i = 0; i < 4; ++i) xr[i] = Xs[i0 + i][c];
            #pragma unroll
            for (int j = 0; j < 4; ++j) wr[j] = Ws[j0 + j][c];
            #pragma unroll
            for (int i = 0; i < 4; ++i)
                #pragma unroll
                for (int j = 0; j < 4; ++j)
                    acc[i][j] = fmaf(xr[i], wr[j], acc[i][j]);
        }
        float* out = (chunk == 0) ? g_q : (chunk == 1) ? g_k : g_v;
        #pragma unroll
        for (int i = 0; i < 4; ++i)
            #pragma unroll
            for (int j = 0; j < 4; ++j)
                out[(size_t)(row0 + i0 + i) * CC + j0 + j] =
                    acc[i][j] + bias[chunk * 64 + j0 + j];
    }
}

// ---------------------------------------------------------------------------
// Kernel 2: fused relative-bias causal attention (flash-style, fp32)
// grid = (16 t-tiles, 8 batch), block = 256 threads (16x16), 64x64 tiles
// ---------------------------------------------------------------------------
struct AttnSmem {
    float Qs[64][65];
    float Ks[64][65];
    float Vs[64][65];
    float Ps[64][65];
    float Ek[127][65];
    float Ev[127][65];
};

__global__ __launch_bounds__(256, 1) void attn_kernel(
    const float* __restrict__ embk, const float* __restrict__ embv)
{
    extern __shared__ char smem_raw[];
    AttnSmem& sm = *reinterpret_cast<AttnSmem*>(smem_raw);

    const int b = blockIdx.y;
    const int t0 = blockIdx.x * 64;
    const int tid = threadIdx.x;
    const int tx = tid & 15, ty = tid >> 4;
    const int i0 = ty * 4, j0 = tx * 4;

    const float* qb = g_q + ((size_t)b * TT + t0) * CC;
    for (int k = tid; k < 64 * 16; k += 256) {
        int r = k >> 4, c4 = k & 15;
        float4 v = reinterpret_cast<const float4*>(qb + (size_t)r * CC)[c4];
        sm.Qs[r][c4 * 4 + 0] = v.x; sm.Qs[r][c4 * 4 + 1] = v.y;
        sm.Qs[r][c4 * 4 + 2] = v.z; sm.Qs[r][c4 * 4 + 3] = v.w;
    }

    float acc[4][4] = {};
    float m[4], lsum[4] = {};
    #pragma unroll
    for (int i = 0; i < 4; ++i) m[i] = -1e30f;

    const int ebase = i0 - j0 + 60;  // Ek row for (i-j) = -3

    for (int s0 = 0; s0 <= t0; s0 += 64) {
        __syncthreads();  // protect smem reuse from previous iteration (and Qs on iter 0)

        const float* kb = g_k + ((size_t)b * TT + s0) * CC;
        const float* vb = g_v + ((size_t)b * TT + s0) * CC;
        for (int k = tid; k < 64 * 16; k += 256) {
            int r = k >> 4, c4 = k & 15;
            float4 kv = reinterpret_cast<const float4*>(kb + (size_t)r * CC)[c4];
            float4 vv = reinterpret_cast<const float4*>(vb + (size_t)r * CC)[c4];
            sm.Ks[r][c4 * 4 + 0] = kv.x; sm.Ks[r][c4 * 4 + 1] = kv.y;
            sm.Ks[r][c4 * 4 + 2] = kv.z; sm.Ks[r][c4 * 4 + 3] = kv.w;
            sm.Vs[r][c4 * 4 + 0] = vv.x; sm.Vs[r][c4 * 4 + 1] = vv.y;
            sm.Vs[r][c4 * 4 + 2] = vv.z; sm.Vs[r][c4 * 4 + 3] = vv.w;
        }
        const int D = t0 - s0;
        for (int k = tid; k < 127 * 16; k += 256) {
            int r = k >> 4, c4 = k & 15;
            int e = D - 63 + r;
            if (e < 0) e = 0;  // rows with d<0 correspond to masked entries; value irrelevant
            float4 ek = reinterpret_cast<const float4*>(embk + (size_t)e * CC)[c4];
            float4 ev = reinterpret_cast<const float4*>(embv + (size_t)e * CC)[c4];
            sm.Ek[r][c4 * 4 + 0] = ek.x; sm.Ek[r][c4 * 4 + 1] = ek.y;
            sm.Ek[r][c4 * 4 + 2] = ek.z; sm.Ek[r][c4 * 4 + 3] = ek.w;
            sm.Ev[r][c4 * 4 + 0] = ev.x; sm.Ev[r][c4 * 4 + 1] = ev.y;
            sm.Ev[r][c4 * 4 + 2] = ev.z; sm.Ev[r][c4 * 4 + 3] = ev.w;
        }
        __syncthreads();

        // --- S tile: S[i][j] = sum_c Q[i][c] * (K[j][c] + Ek[(i-j)+63][c]) ---
        float S[4][4] = {};
        #pragma unroll 4
        for (int c = 0; c < 64; ++c) {
            float qr[4], kr[4], er[7];
            #pragma unroll
            for (int i = 0; i < 4; ++i) qr[i] = sm.Qs[i0 + i][c];
            #pragma unroll
            for (int j = 0; j < 4; ++j) kr[j] = sm.Ks[j0 + j][c];
            #pragma unroll
            for (int k = 0; k < 7; ++k) er[k] = sm.Ek[ebase + k][c];
            #pragma unroll
            for (int i = 0; i < 4; ++i)
                #pragma unroll
                for (int j = 0; j < 4; ++j)
                    S[i][j] = fmaf(qr[i], kr[j] + er[i - j + 3], S[i][j]);
        }

        // scale + causal mask
        const float scale = 0.125f;  // 1/sqrt(64)
        #pragma unroll
        for (int i = 0; i < 4; ++i)
            #pragma unroll
            for (int j = 0; j < 4; ++j) {
                S[i][j] *= scale;
                int t = t0 + i0 + i, s = s0 + j0 + j;
                if (s > t) S[i][j] = -1e30f;
            }

        // online softmax update (row groups = 16 lanes sharing ty)
        #pragma unroll
        for (int i = 0; i < 4; ++i) {
            float mt = fmaxf(fmaxf(S[i][0], S[i][1]), fmaxf(S[i][2], S[i][3]));
            #pragma unroll
            for (int d = 1; d < 16; d <<= 1)
                mt = fmaxf(mt, __shfl_xor_sync(0xffffffffu, mt, d));
            float mnew = fmaxf(m[i], mt);
            float alpha = __expf(m[i] - mnew);
            m[i] = mnew;
            lsum[i] *= alpha;
            #pragma unroll
            for (int j = 0; j < 4; ++j) acc[i][j] *= alpha;
            float ps = 0.f;
            #pragma unroll
            for (int j = 0; j < 4; ++j) {
                float p = __expf(S[i][j] - mnew);
                S[i][j] = p;
                ps += p;
            }
            lsum[i] += ps;
            #pragma unroll
            for (int j = 0; j < 4; ++j) sm.Ps[i0 + i][j0 + j] = S[i][j];
        }
        __syncthreads();  // all P written before consumption

        // --- y accumulation: acc[i][j] += sum_si P[i][si]*(V[si][j] + Ev[i-si+63][j]) ---
        #pragma unroll 2
        for (int si = 0; si < 64; ++si) {
            float pr[4], vr[4];
            #pragma unroll
            for (int i = 0; i < 4; ++i) pr[i] = sm.Ps[i0 + i][si];
            #pragma unroll
            for (int j = 0; j < 4; ++j) vr[j] = sm.Vs[si][j0 + j];
            const int erow = i0 - si + 63;
            #pragma unroll
            for (int i = 0; i < 4; ++i) {
                const float p = pr[i];
                const float* evr = &sm.Ev[erow + i][0];
                #pragma unroll
                for (int j = 0; j < 4; ++j)
                    acc[i][j] = fmaf(p, vr[j] + evr[j0 + j], acc[i][j]);
            }
        }
    }

    // finalize: divide by row sum (reduced across the 16-lane row group)
    float* yb = g_y + ((size_t)b * TT + t0) * CC;
    #pragma unroll
    for (int i = 0; i < 4; ++i) {
        float l = lsum[i];
        #pragma unroll
        for (int d = 1; d < 16; d <<= 1)
            l += __shfl_xor_sync(0xffffffffu, l, d);
        float inv = 1.0f / l;
        #pragma unroll
        for (int j = 0; j < 4; ++j)
            yb[(size_t)(i0 + i) * CC + j0 + j] = acc[i][j] * inv;
    }
}

// ---------------------------------------------------------------------------
// Kernel 3: out = y @ Wproj^T + bproj
// ---------------------------------------------------------------------------
__global__ __launch_bounds__(256) void proj_kernel(
    const float* __restrict__ W, const float* __restrict__ bias,
    float* __restrict__ out)
{
    __shared__ float Xs[64][65];
    __shared__ float Ws[64][65];
    const int row0 = blockIdx.x * 64;
    const int tid = threadIdx.x;
    const int tx = tid & 15, ty = tid >> 4;
    const int i0 = ty * 4, j0 = tx * 4;

    for (int k = tid; k < 64 * 16; k += 256) {
        int r = k >> 4, c4 = k & 15;
        float4 xv = reinterpret_cast<const float4*>(g_y + (size_t)(row0 + r) * CC)[c4];
        float4 wv = reinterpret_cast<const float4*>(W + (size_t)r * CC)[c4];
        Xs[r][c4 * 4 + 0] = xv.x; Xs[r][c4 * 4 + 1] = xv.y;
        Xs[r][c4 * 4 + 2] = xv.z; Xs[r][c4 * 4 + 3] = xv.w;
        Ws[r][c4 * 4 + 0] = wv.x; Ws[r][c4 * 4 + 1] = wv.y;
        Ws[r][c4 * 4 + 2] = wv.z; Ws[r][c4 * 4 + 3] = wv.w;
    }
    __syncthreads();

    float acc[4][4] = {};
    #pragma unroll
    for (int c = 0; c < 64; ++c) {
        float xr[4], wr[4];
        #pragma unroll
        for (int i = 0; i < 4; ++i) xr[i] = Xs[i0 + i][c];
        #pragma unroll
        for (int j = 0; j < 4; ++j) wr[j] = Ws[j0 + j][c];
        #pragma unroll
        for (int i = 0; i < 4; ++i)
            #pragma unroll
            for (int j = 0; j < 4; ++j)
                acc[i][j] = fmaf(xr[i], wr[j], acc[i][j]);
    }
    #pragma unroll
    for (int i = 0; i < 4; ++i)
        #pragma unroll
        for (int j = 0; j < 4; ++j)
            out[(size_t)(row0 + i0 + i) * CC + j0 + j] = acc[i][j] + bias[j0 + j];
}

// ---------------------------------------------------------------------------
extern "C" void kernel_launch(void* const* d_in, const int* in_sizes, int n_in,
                              void* d_out, int out_size)
{
    const float* x     = (const float*)d_in[0];
    const float* Wqkv  = (const float*)d_in[1];
    const float* bqkv  = (const float*)d_in[2];
    const float* embk  = (const float*)d_in[3];
    const float* embv  = (const float*)d_in[4];
    const float* Wproj = (const float*)d_in[5];
    const float* bproj = (const float*)d_in[6];
    float* out = (float*)d_out;

    (void)in_sizes; (void)n_in; (void)out_size;

    // opt-in to >48KB dynamic smem (idempotent; safe under graph capture)
    cudaFuncSetAttribute(attn_kernel, cudaFuncAttributeMaxDynamicSharedMemorySize,
                         (int)sizeof(AttnSmem));

    qkv_kernel<<<BB * TT / 64, 256>>>(x, Wqkv, bqkv);
    attn_kernel<<<dim3(TT / 64, BB), 256, sizeof(AttnSmem)>>>(embk, embv);
    proj_kernel<<<BB * TT / 64, 256>>>(Wproj, bproj, out);
}

// round 4
// speedup vs baseline: 1.4694x; 1.4694x over previous
#include <cuda_runtime.h>
#include <mma.h>
#include <math.h>

using namespace nvcuda;

#define BB 8
#define TT 1024
#define CC 64
#define LD  72    // padded leading dim for 64-col tiles (mult of 8)
#define LD2 136   // padded leading dim for 128-col tiles (mult of 8)

// Scratch (no allocation allowed in kernel_launch)
__device__ float g_q[BB*TT*CC];
__device__ float g_k[BB*TT*CC];
__device__ float g_v[BB*TT*CC];
__device__ float g_y[BB*TT*CC];

// ---------------------------------------------------------------------------
// Kernel 1: qkv = x @ Wqkv^T + bqkv -> g_q/g_k/g_v
// grid = (128, 3): blockIdx.y selects the q/k/v chunk. 256 thr, 4x4 microtile.
// ---------------------------------------------------------------------------
__global__ __launch_bounds__(256) void qkv_kernel(
    const float* __restrict__ x, const float* __restrict__ W,
    const float* __restrict__ bias)
{
    __shared__ float Xs[64][65];
    __shared__ float Ws[64][65];
    const int chunk = blockIdx.y;
    const int row0 = blockIdx.x * 64;
    const int tid = threadIdx.x;
    const int tx = tid & 15, ty = tid >> 4;
    const int i0 = ty * 4, j0 = tx * 4;

    for (int k = tid; k < 64 * 16; k += 256) {
        int r = k >> 4, c4 = k & 15;
        float4 v = reinterpret_cast<const float4*>(x + (size_t)(row0 + r) * CC)[c4];
        Xs[r][c4 * 4 + 0] = v.x; Xs[r][c4 * 4 + 1] = v.y;
        Xs[r][c4 * 4 + 2] = v.z; Xs[r][c4 * 4 + 3] = v.w;
        float4 w = reinterpret_cast<const float4*>(W + (size_t)(chunk * 64 + r) * CC)[c4];
        Ws[r][c4 * 4 + 0] = w.x; Ws[r][c4 * 4 + 1] = w.y;
        Ws[r][c4 * 4 + 2] = w.z; Ws[r][c4 * 4 + 3] = w.w;
    }
    __syncthreads();

    float acc[4][4] = {};
    #pragma unroll
    for (int c = 0; c < 64; ++c) {
        float xr[4], wr[4];
        #pragma unroll
        for (int i = 0; i < 4; ++i) xr[i] = Xs[i0 + i][c];
        #pragma unroll
        for (int j = 0; j < 4; ++j) wr[j] = Ws[j0 + j][c];
        #pragma unroll
        for (int i = 0; i < 4; ++i)
            #pragma unroll
            for (int j = 0; j < 4; ++j)
                acc[i][j] = fmaf(xr[i], wr[j], acc[i][j]);
    }
    float* out = (chunk == 0) ? g_q : (chunk == 1) ? g_k : g_v;
    #pragma unroll
    for (int i = 0; i < 4; ++i)
        #pragma unroll
        for (int j = 0; j < 4; ++j)
            out[(size_t)(row0 + i0 + i) * CC + j0 + j] =
                acc[i][j] + bias[chunk * 64 + j0 + j];
}

// ---------------------------------------------------------------------------
// Kernel 2: fused relative-bias causal attention, wmma tf32
// grid = (16 t-tiles, 8 batch), block = 256 threads (8 warps), 64x64 tiles
// ---------------------------------------------------------------------------
struct AttnSmem {
    float Qs[64 * LD];
    float Ks[64 * LD];    // aliased as Yd (PV+PdEv delta) in late phase
    float Vs[64 * LD];
    float Ek[128 * LD];
    float Ev[128 * LD];
    float SP[64 * LD];    // S1 (QK^T), then P in place
    float S2[64 * LD2];   // S2 (Q Ek^T), then Pd in place
    float Y [64 * LD];    // running output accumulator
    float alpha[64];
};

typedef wmma::fragment<wmma::matrix_a, 16, 16, 8, wmma::precision::tf32, wmma::row_major> FragA;
typedef wmma::fragment<wmma::matrix_b, 16, 16, 8, wmma::precision::tf32, wmma::col_major> FragBc;
typedef wmma::fragment<wmma::matrix_b, 16, 16, 8, wmma::precision::tf32, wmma::row_major> FragBr;
typedef wmma::fragment<wmma::accumulator, 16, 16, 8, float> FragC;

__device__ __forceinline__ void load_a(FragA& f, const float* p, int ld) {
    wmma::load_matrix_sync(f, p, ld);
    #pragma unroll
    for (int t = 0; t < f.num_elements; ++t) f.x[t] = wmma::__float_to_tf32(f.x[t]);
}
__device__ __forceinline__ void load_bc(FragBc& f, const float* p, int ld) {
    wmma::load_matrix_sync(f, p, ld);
    #pragma unroll
    for (int t = 0; t < f.num_elements; ++t) f.x[t] = wmma::__float_to_tf32(f.x[t]);
}
__device__ __forceinline__ void load_br(FragBr& f, const float* p, int ld) {
    wmma::load_matrix_sync(f, p, ld);
    #pragma unroll
    for (int t = 0; t < f.num_elements; ++t) f.x[t] = wmma::__float_to_tf32(f.x[t]);
}

__global__ __launch_bounds__(256, 1) void attn_kernel(
    const float* __restrict__ embk, const float* __restrict__ embv)
{
    extern __shared__ char smem_raw[];
    AttnSmem& sm = *reinterpret_cast<AttnSmem*>(smem_raw);

    const int b  = blockIdx.y;
    const int t0 = blockIdx.x * 64;
    const int tid = threadIdx.x;
    const int w  = tid >> 5;              // warp id 0..7
    const int wti = w >> 1;               // warp's row-tile (0..3)
    const int wcj = w & 1;                // warp's column half

    // softmax thread mapping: 4 threads per row
    const int row = tid >> 2;             // 0..63
    const int cq  = tid & 3;              // col quarter
    const int jb  = cq * 16;

    // Load Q tile once
    const float* qb = g_q + ((size_t)b * TT + t0) * CC;
    for (int k = tid; k < 64 * 16; k += 256) {
        int r = k >> 4, c4 = k & 15;
        reinterpret_cast<float4*>(&sm.Qs[r * LD])[c4] =
            reinterpret_cast<const float4*>(qb + (size_t)r * CC)[c4];
    }
    // Zero Y accumulator
    for (int k = tid; k < 64 * 16; k += 256) {
        int r = k >> 4, c4 = k & 15;
        reinterpret_cast<float4*>(&sm.Y[r * LD])[c4] = make_float4(0.f, 0.f, 0.f, 0.f);
    }

    float m = -1e30f, l = 0.f;

    for (int s0 = 0; s0 <= t0; s0 += 64) {
        __syncthreads();   // protect Ks(=Yd)/Vs/Ek/Ev reuse from previous iter + Qs/Y on iter 0

        // ---- stage K, V (64 rows) and Ek, Ev windows (128 rows) ----
        const float* kb = g_k + ((size_t)b * TT + s0) * CC;
        const float* vb = g_v + ((size_t)b * TT + s0) * CC;
        for (int k = tid; k < 64 * 16; k += 256) {
            int r = k >> 4, c4 = k & 15;
            reinterpret_cast<float4*>(&sm.Ks[r * LD])[c4] =
                reinterpret_cast<const float4*>(kb + (size_t)r * CC)[c4];
            reinterpret_cast<float4*>(&sm.Vs[r * LD])[c4] =
                reinterpret_cast<const float4*>(vb + (size_t)r * CC)[c4];
        }
        const int D = t0 - s0;
        for (int k = tid; k < 128 * 16; k += 256) {
            int r = k >> 4, c4 = k & 15;
            int e = D - 63 + r;
            e = (e < 0) ? 0 : (e > TT - 1 ? TT - 1 : e);
            reinterpret_cast<float4*>(&sm.Ek[r * LD])[c4] =
                reinterpret_cast<const float4*>(embk + (size_t)e * CC)[c4];
            reinterpret_cast<float4*>(&sm.Ev[r * LD])[c4] =
                reinterpret_cast<const float4*>(embv + (size_t)e * CC)[c4];
        }
        __syncthreads();

        // ---- GEMM phase 1: S1 = Q K^T  [64x64],  S2 = Q Ek^T  [64x128] ----
        {
            FragA aq[8];
            #pragma unroll
            for (int k0 = 0; k0 < 8; ++k0)
                load_a(aq[k0], &sm.Qs[wti * 16 * LD + k0 * 8], LD);

            #pragma unroll
            for (int t2 = 0; t2 < 2; ++t2) {
                int tj = wcj * 2 + t2;
                FragC c; wmma::fill_fragment(c, 0.f);
                #pragma unroll
                for (int k0 = 0; k0 < 8; ++k0) {
                    FragBc bk;  // (k=c, n=s) = Ks[s][c] -> col-major
                    load_bc(bk, &sm.Ks[tj * 16 * LD + k0 * 8], LD);
                    wmma::mma_sync(c, aq[k0], bk, c);
                }
                wmma::store_matrix_sync(&sm.SP[wti * 16 * LD + tj * 16], c, LD,
                                        wmma::mem_row_major);
            }
            #pragma unroll
            for (int t2 = 0; t2 < 4; ++t2) {
                int tj = wcj * 4 + t2;
                FragC c; wmma::fill_fragment(c, 0.f);
                #pragma unroll
                for (int k0 = 0; k0 < 8; ++k0) {
                    FragBc be;  // (k=c, n=r) = Ek[r][c] -> col-major
                    load_bc(be, &sm.Ek[tj * 16 * LD + k0 * 8], LD);
                    wmma::mma_sync(c, aq[k0], be, c);
                }
                wmma::store_matrix_sync(&sm.S2[wti * 16 * LD2 + tj * 16], c, LD2,
                                        wmma::mem_row_major);
            }
        }
        __syncthreads();

        // ---- scalar softmax phase (4 threads per row, 16 cols each) ----
        float pv[16];
        {
            float sv[16];
            float mt = -1e30f;
            #pragma unroll
            for (int jj = 0; jj < 16; ++jj) {
                int j = jb + jj;
                int dd = row - j + 63;                       // 0..126
                float s = (sm.SP[row * LD + j] + sm.S2[row * LD2 + dd]) * 0.125f;
                if (D + row - j < 0) s = -1e30f;             // causal mask
                sv[jj] = s;
                mt = fmaxf(mt, s);
            }
            mt = fmaxf(mt, __shfl_xor_sync(0xffffffffu, mt, 1));
            mt = fmaxf(mt, __shfl_xor_sync(0xffffffffu, mt, 2));
            float mnew = fmaxf(m, mt);
            float al = __expf(m - mnew);
            m = mnew;
            float ps = 0.f;
            #pragma unroll
            for (int jj = 0; jj < 16; ++jj) {
                float p = __expf(sv[jj] - mnew);             // masked -> exp(-huge) = 0
                pv[jj] = p;
                ps += p;
                sm.SP[row * LD + jb + jj] = p;               // P in place over S1
            }
            ps += __shfl_xor_sync(0xffffffffu, ps, 1);
            ps += __shfl_xor_sync(0xffffffffu, ps, 2);
            l = l * al + ps;
            if (cq == 0) sm.alpha[row] = al;
        }
        __syncthreads();   // everyone's S2 reads done -> safe to clobber as Pd

        // ---- zero Pd (64 x 128 region of S2 buffer) ----
        for (int k = tid; k < 64 * 32; k += 256) {
            int r = k >> 5, c4 = k & 31;
            reinterpret_cast<float4*>(&sm.S2[r * LD2])[c4] = make_float4(0.f, 0.f, 0.f, 0.f);
        }
        __syncthreads();

        // ---- scatter P into diagonal coordinates: Pd[i][i-j+63] = P[i][j] ----
        #pragma unroll
        for (int jj = 0; jj < 16; ++jj) {
            int dd = row - (jb + jj) + 63;
            sm.S2[row * LD2 + dd] = pv[jj];
        }
        __syncthreads();

        // ---- GEMM phase 2: Yd = P V + Pd Ev  [64x64], store into Ks alias ----
        {
            FragA pa[8];
            #pragma unroll
            for (int k0 = 0; k0 < 8; ++k0)
                load_a(pa[k0], &sm.SP[wti * 16 * LD + k0 * 8], LD);

            #pragma unroll
            for (int t2 = 0; t2 < 2; ++t2) {
                int tj = wcj * 2 + t2;
                FragC c; wmma::fill_fragment(c, 0.f);
                #pragma unroll
                for (int k0 = 0; k0 < 8; ++k0) {
                    FragBr bv;  // (k=s, n=c) = Vs[s][c] -> row-major
                    load_br(bv, &sm.Vs[k0 * 8 * LD + tj * 16], LD);
                    wmma::mma_sync(c, pa[k0], bv, c);
                }
                #pragma unroll
                for (int k0 = 0; k0 < 16; ++k0) {
                    FragA ad;   // Pd row-major, ld = LD2
                    load_a(ad, &sm.S2[wti * 16 * LD2 + k0 * 8], LD2);
                    FragBr be;  // (k=r, n=c) = Ev[r][c] -> row-major
                    load_br(be, &sm.Ev[k0 * 8 * LD + tj * 16], LD);
                    wmma::mma_sync(c, ad, be, c);
                }
                wmma::store_matrix_sync(&sm.Ks[wti * 16 * LD + tj * 16], c, LD,
                                        wmma::mem_row_major);
            }
        }
        __syncthreads();

        // ---- rescale-and-accumulate: Y = Y*alpha[row] + Yd ----
        {
            float al = sm.alpha[row];
            #pragma unroll
            for (int q4 = 0; q4 < 4; ++q4) {
                float4 y = reinterpret_cast<float4*>(&sm.Y[row * LD + jb])[q4];
                float4 d = reinterpret_cast<float4*>(&sm.Ks[row * LD + jb])[q4];
                y.x = y.x * al + d.x; y.y = y.y * al + d.y;
                y.z = y.z * al + d.z; y.w = y.w * al + d.w;
                reinterpret_cast<float4*>(&sm.Y[row * LD + jb])[q4] = y;
            }
        }
    }

    // ---- finalize: divide by row sum, write out ----
    float inv = 1.0f / l;
    float* yb = g_y + ((size_t)b * TT + t0) * CC;
    #pragma unroll
    for (int jj = 0; jj < 16; ++jj)
        yb[(size_t)row * CC + jb + jj] = sm.Y[row * LD + jb + jj] * inv;
}

// ---------------------------------------------------------------------------
// Kernel 3: out = y @ Wproj^T + bproj
// ---------------------------------------------------------------------------
__global__ __launch_bounds__(256) void proj_kernel(
    const float* __restrict__ W, const float* __restrict__ bias,
    float* __restrict__ out)
{
    __shared__ float Xs[64][65];
    __shared__ float Ws[64][65];
    const int row0 = blockIdx.x * 64;
    const int tid = threadIdx.x;
    const int tx = tid & 15, ty = tid >> 4;
    const int i0 = ty * 4, j0 = tx * 4;

    for (int k = tid; k < 64 * 16; k += 256) {
        int r = k >> 4, c4 = k & 15;
        float4 xv = reinterpret_cast<const float4*>(g_y + (size_t)(row0 + r) * CC)[c4];
        float4 wv = reinterpret_cast<const float4*>(W + (size_t)r * CC)[c4];
        Xs[r][c4 * 4 + 0] = xv.x; Xs[r][c4 * 4 + 1] = xv.y;
        Xs[r][c4 * 4 + 2] = xv.z; Xs[r][c4 * 4 + 3] = xv.w;
        Ws[r][c4 * 4 + 0] = wv.x; Ws[r][c4 * 4 + 1] = wv.y;
        Ws[r][c4 * 4 + 2] = wv.z; Ws[r][c4 * 4 + 3] = wv.w;
    }
    __syncthreads();

    float acc[4][4] = {};
    #pragma unroll
    for (int c = 0; c < 64; ++c) {
        float xr[4], wr[4];
        #pragma unroll
        for (int i = 0; i < 4; ++i) xr[i] = Xs[i0 + i][c];
        #pragma unroll
        for (int j = 0; j < 4; ++j) wr[j] = Ws[j0 + j][c];
        #pragma unroll
        for (int i = 0; i < 4; ++i)
            #pragma unroll
            for (int j = 0; j < 4; ++j)
                acc[i][j] = fmaf(xr[i], wr[j], acc[i][j]);
    }
    #pragma unroll
    for (int i = 0; i < 4; ++i)
        #pragma unroll
        for (int j = 0; j < 4; ++j)
            out[(size_t)(row0 + i0 + i) * CC + j0 + j] = acc[i][j] + bias[j0 + j];
}

// ---------------------------------------------------------------------------
extern "C" void kernel_launch(void* const* d_in, const int* in_sizes, int n_in,
                              void* d_out, int out_size)
{
    const float* x     = (const float*)d_in[0];
    const float* Wqkv  = (const float*)d_in[1];
    const float* bqkv  = (const float*)d_in[2];
    const float* embk  = (const float*)d_in[3];
    const float* embv  = (const float*)d_in[4];
    const float* Wproj = (const float*)d_in[5];
    const float* bproj = (const float*)d_in[6];
    float* out = (float*)d_out;

    (void)in_sizes; (void)n_in; (void)out_size;

    cudaFuncSetAttribute(attn_kernel, cudaFuncAttributeMaxDynamicSharedMemorySize,
                         (int)sizeof(AttnSmem));

    qkv_kernel<<<dim3(BB * TT / 64, 3), 256>>>(x, Wqkv, bqkv);
    attn_kernel<<<dim3(TT / 64, BB), 256, sizeof(AttnSmem)>>>(embk, embv);
    proj_kernel<<<BB * TT / 64, 256>>>(Wproj, bproj, out);
}

// round 7
// speedup vs baseline: 2.3454x; 1.5961x over previous
#include <cuda_runtime.h>
#include <mma.h>
#include <math.h>

using namespace nvcuda;

#define BB 8
#define TT 1024
#define CC 64
#define LD  72    // padded leading dim for 64-col tiles
#define LD2 136   // padded leading dim for 128-col tiles

// Scratch (no allocation allowed in kernel_launch)
__device__ float g_q[BB*TT*CC];
__device__ float g_k[BB*TT*CC];
__device__ float g_v[BB*TT*CC];
__device__ float g_y[BB*TT*CC];

// split-softmax partial state: slot = ((b*16 + tau)*8 + kappa)
__device__ float g_pm[BB*16*8*64];
__device__ float g_pl[BB*16*8*64];
__device__ float g_py[(size_t)BB*16*8*64*64];

// Job table: value = tau*16 + kappa. Chunk = 2 s-tiles. Ordered big-jobs-first.
__device__ const int c_jobs[72] = {
    // ns = 2 jobs, tau descending
    240,241,242,243,244,245,246,247,
    224,225,226,227,228,229,230,
    208,209,210,211,212,213,214,
    192,193,194,195,196,197,
    176,177,178,179,180,181,
    160,161,162,163,164,
    144,145,146,147,148,
    128,129,130,131,
    112,113,114,115,
    96,97,98,
    80,81,82,
    64,65,
    48,49,
    32,
    16,
    // ns = 1 jobs
    231,198,165,132,99,66,33,0
};

// ---------------------------------------------------------------------------
// Kernel 1: qkv = x @ Wqkv^T + bqkv -> g_q/g_k/g_v
// grid = (256, 3): 32-row tiles; blockIdx.y selects q/k/v chunk.
// ---------------------------------------------------------------------------
__global__ __launch_bounds__(256) void qkv_kernel(
    const float* __restrict__ x, const float* __restrict__ W,
    const float* __restrict__ bias)
{
    __shared__ float Xs[32][65];
    __shared__ float Ws[64][65];
    const int chunk = blockIdx.y;
    const int row0 = blockIdx.x * 32;
    const int tid = threadIdx.x;
    const int tx = tid & 15, ty = tid >> 4;
    const int i0 = ty * 2, j0 = tx * 4;

    for (int k = tid; k < 32 * 16; k += 256) {
        int r = k >> 4, c4 = k & 15;
        float4 v = reinterpret_cast<const float4*>(x + (size_t)(row0 + r) * CC)[c4];
        Xs[r][c4 * 4 + 0] = v.x; Xs[r][c4 * 4 + 1] = v.y;
        Xs[r][c4 * 4 + 2] = v.z; Xs[r][c4 * 4 + 3] = v.w;
    }
    for (int k = tid; k < 64 * 16; k += 256) {
        int r = k >> 4, c4 = k & 15;
        float4 w = reinterpret_cast<const float4*>(W + (size_t)(chunk * 64 + r) * CC)[c4];
        Ws[r][c4 * 4 + 0] = w.x; Ws[r][c4 * 4 + 1] = w.y;
        Ws[r][c4 * 4 + 2] = w.z; Ws[r][c4 * 4 + 3] = w.w;
    }
    __syncthreads();

    float acc[2][4] = {};
    #pragma unroll
    for (int c = 0; c < 64; ++c) {
        float xr[2], wr[4];
        #pragma unroll
        for (int i = 0; i < 2; ++i) xr[i] = Xs[i0 + i][c];
        #pragma unroll
        for (int j = 0; j < 4; ++j) wr[j] = Ws[j0 + j][c];
        #pragma unroll
        for (int i = 0; i < 2; ++i)
            #pragma unroll
            for (int j = 0; j < 4; ++j)
                acc[i][j] = fmaf(xr[i], wr[j], acc[i][j]);
    }
    float* out = (chunk == 0) ? g_q : (chunk == 1) ? g_k : g_v;
    #pragma unroll
    for (int i = 0; i < 2; ++i)
        #pragma unroll
        for (int j = 0; j < 4; ++j)
            out[(size_t)(row0 + i0 + i) * CC + j0 + j] =
                acc[i][j] + bias[chunk * 64 + j0 + j];
}

// ---------------------------------------------------------------------------
// Kernel 2: partial flash attention over a chunk of <=2 s-tiles, wmma tf32
// grid = (72 jobs, 8 batch), 512 threads (16 warps)
// ---------------------------------------------------------------------------
struct alignas(16) AttnSmem {
    float Qs[64 * LD];
    float Ks[64 * LD];    // aliased as Yd in phase 2
    float Vs[64 * LD];
    float Ek[128 * LD];
    float Ev[128 * LD];
    float SP[64 * LD];    // S1 (QK^T) -> P in place
    float S2[64 * LD2];   // S2 (Q Ek^T) -> Pd in place
};

typedef wmma::fragment<wmma::matrix_a, 16, 16, 8, wmma::precision::tf32, wmma::row_major> FragA;
typedef wmma::fragment<wmma::matrix_b, 16, 16, 8, wmma::precision::tf32, wmma::col_major> FragBc;
typedef wmma::fragment<wmma::matrix_b, 16, 16, 8, wmma::precision::tf32, wmma::row_major> FragBr;
typedef wmma::fragment<wmma::accumulator, 16, 16, 8, float> FragC;

__device__ __forceinline__ void load_a(FragA& f, const float* p, int ld) {
    wmma::load_matrix_sync(f, p, ld);
    #pragma unroll
    for (int t = 0; t < f.num_elements; ++t) f.x[t] = wmma::__float_to_tf32(f.x[t]);
}
__device__ __forceinline__ void load_bc(FragBc& f, const float* p, int ld) {
    wmma::load_matrix_sync(f, p, ld);
    #pragma unroll
    for (int t = 0; t < f.num_elements; ++t) f.x[t] = wmma::__float_to_tf32(f.x[t]);
}
__device__ __forceinline__ void load_br(FragBr& f, const float* p, int ld) {
    wmma::load_matrix_sync(f, p, ld);
    #pragma unroll
    for (int t = 0; t < f.num_elements; ++t) f.x[t] = wmma::__float_to_tf32(f.x[t]);
}

__global__ __launch_bounds__(512, 1) void attn_partial_kernel(
    const float* __restrict__ embk, const float* __restrict__ embv)
{
    extern __shared__ char smem_raw[];
    AttnSmem& sm = *reinterpret_cast<AttnSmem*>(smem_raw);

    const int b = blockIdx.y;
    const int job = c_jobs[blockIdx.x];
    const int tau = job >> 4;
    const int kap = job & 15;
    const int t0 = tau * 64;
    const int stile0 = kap * 2;
    const int ns = min(2, tau + 1 - 2 * kap);

    const int tid = threadIdx.x;
    const int w = tid >> 5;

    // softmax / Y-ownership mapping: 8 threads per row, 8 cols each
    const int row = tid >> 3;
    const int o = tid & 7;
    const int jb = o * 8;

    // ---- load Q tile ----
    const float* qb = g_q + ((size_t)b * TT + t0) * CC;
    for (int k = tid; k < 64 * 16; k += 512) {
        int r = k >> 4, c4 = k & 15;
        reinterpret_cast<float4*>(&sm.Qs[r * LD])[c4] =
            reinterpret_cast<const float4*>(qb + (size_t)r * CC)[c4];
    }

    float m = -1e30f, l = 0.f;
    float y[8] = {};

    for (int it = 0; it < ns; ++it) {
        const int sig = stile0 + it;
        const int s0 = sig * 64;
        const int D = t0 - s0;   // >= 0

        __syncthreads();   // protect Ks(=Yd) from rescale reads / smem reuse

        // ---- stage K, V, Ek window, Ev window ----
        const float* kb = g_k + ((size_t)b * TT + s0) * CC;
        const float* vb = g_v + ((size_t)b * TT + s0) * CC;
        for (int k = tid; k < 64 * 16; k += 512) {
            int r = k >> 4, c4 = k & 15;
            reinterpret_cast<float4*>(&sm.Ks[r * LD])[c4] =
                reinterpret_cast<const float4*>(kb + (size_t)r * CC)[c4];
            reinterpret_cast<float4*>(&sm.Vs[r * LD])[c4] =
                reinterpret_cast<const float4*>(vb + (size_t)r * CC)[c4];
        }
        for (int k = tid; k < 128 * 16; k += 512) {
            int r = k >> 4, c4 = k & 15;
            int e = D - 63 + r;
            e = (e < 0) ? 0 : (e > TT - 1 ? TT - 1 : e);
            reinterpret_cast<float4*>(&sm.Ek[r * LD])[c4] =
                reinterpret_cast<const float4*>(embk + (size_t)e * CC)[c4];
            reinterpret_cast<float4*>(&sm.Ev[r * LD])[c4] =
                reinterpret_cast<const float4*>(embv + (size_t)e * CC)[c4];
        }
        __syncthreads();

        // ---- GEMM 1: S1 = Q K^T (16 tiles), S2 = Q Ek^T (32 tiles); 3 tiles/warp
        {
            const int rt = w >> 2;
            const int ct0 = 3 * (w & 3);
            FragA aq[8];
            #pragma unroll
            for (int k0 = 0; k0 < 8; ++k0)
                load_a(aq[k0], &sm.Qs[rt * 16 * LD + k0 * 8], LD);

            #pragma unroll
            for (int tci = 0; tci < 3; ++tci) {
                const int ct = ct0 + tci;
                FragC c; wmma::fill_fragment(c, 0.f);
                if (ct < 4) {
                    #pragma unroll
                    for (int k0 = 0; k0 < 8; ++k0) {
                        FragBc bk;
                        load_bc(bk, &sm.Ks[ct * 16 * LD + k0 * 8], LD);
                        wmma::mma_sync(c, aq[k0], bk, c);
                    }
                    wmma::store_matrix_sync(&sm.SP[rt * 16 * LD + ct * 16], c, LD,
                                            wmma::mem_row_major);
                } else {
                    const int ce = ct - 4;
                    #pragma unroll
                    for (int k0 = 0; k0 < 8; ++k0) {
                        FragBc be;
                        load_bc(be, &sm.Ek[ce * 16 * LD + k0 * 8], LD);
                        wmma::mma_sync(c, aq[k0], be, c);
                    }
                    wmma::store_matrix_sync(&sm.S2[rt * 16 * LD2 + ce * 16], c, LD2,
                                            wmma::mem_row_major);
                }
            }
        }
        __syncthreads();

        // ---- softmax: combine S1+S2(diag), mask, online update; write P and Pd
        float alpha;
        {
            float sv[8];
            float mt = -1e30f;
            #pragma unroll
            for (int jj = 0; jj < 8; ++jj) {
                int j = jb + jj;
                int dd = row - j + 63;   // in [0,127)
                float s = (sm.SP[row * LD + j] + sm.S2[row * LD2 + dd]) * 0.125f;
                if (s0 + j > t0 + row) s = -1e30f;
                sv[jj] = s;
                mt = fmaxf(mt, s);
            }
            mt = fmaxf(mt, __shfl_xor_sync(0xffffffffu, mt, 1));
            mt = fmaxf(mt, __shfl_xor_sync(0xffffffffu, mt, 2));
            mt = fmaxf(mt, __shfl_xor_sync(0xffffffffu, mt, 4));
            float mnew = fmaxf(m, mt);
            alpha = __expf(m - mnew);
            m = mnew;
            float ps = 0.f;
            #pragma unroll
            for (int jj = 0; jj < 8; ++jj) {
                int j = jb + jj;
                float p = __expf(sv[jj] - mnew);
                ps += p;
                sm.SP[row * LD + j] = p;                  // P
                sm.S2[row * LD2 + (row - j + 63)] = p;    // Pd band [row, row+63]
            }
            // zero the complement of the band: (row+64 .. row+127) mod 128
            #pragma unroll
            for (int jj = 0; jj < 8; ++jj) {
                int z = (row + 64 + jb + jj) & 127;
                sm.S2[row * LD2 + z] = 0.f;
            }
            ps += __shfl_xor_sync(0xffffffffu, ps, 1);
            ps += __shfl_xor_sync(0xffffffffu, ps, 2);
            ps += __shfl_xor_sync(0xffffffffu, ps, 4);
            l = l * alpha + ps;
        }
        __syncthreads();

        // ---- GEMM 2: Yd = P V + Pd Ev  (16 tiles, 1/warp), store into Ks alias
        {
            const int rt = w >> 2, ct = w & 3;
            FragC c; wmma::fill_fragment(c, 0.f);
            #pragma unroll
            for (int k0 = 0; k0 < 8; ++k0) {
                FragA pa;
                load_a(pa, &sm.SP[rt * 16 * LD + k0 * 8], LD);
                FragBr bv;
                load_br(bv, &sm.Vs[k0 * 8 * LD + ct * 16], LD);
                wmma::mma_sync(c, pa, bv, c);
            }
            #pragma unroll
            for (int k0 = 0; k0 < 16; ++k0) {
                FragA ad;
                load_a(ad, &sm.S2[rt * 16 * LD2 + k0 * 8], LD2);
                FragBr be;
                load_br(be, &sm.Ev[k0 * 8 * LD + ct * 16], LD);
                wmma::mma_sync(c, ad, be, c);
            }
            wmma::store_matrix_sync(&sm.Ks[rt * 16 * LD + ct * 16], c, LD,
                                    wmma::mem_row_major);
        }
        __syncthreads();

        // ---- rescale-and-accumulate in registers ----
        {
            float4 d0 = *reinterpret_cast<float4*>(&sm.Ks[row * LD + jb]);
            float4 d1 = *reinterpret_cast<float4*>(&sm.Ks[row * LD + jb + 4]);
            y[0] = y[0] * alpha + d0.x; y[1] = y[1] * alpha + d0.y;
            y[2] = y[2] * alpha + d0.z; y[3] = y[3] * alpha + d0.w;
            y[4] = y[4] * alpha + d1.x; y[5] = y[5] * alpha + d1.y;
            y[6] = y[6] * alpha + d1.z; y[7] = y[7] * alpha + d1.w;
        }
    }

    // ---- write partial state ----
    const int slot = (b * 16 + tau) * 8 + kap;
    float* yp = g_py + (size_t)slot * 4096;
    float4 w0 = make_float4(y[0], y[1], y[2], y[3]);
    float4 w1 = make_float4(y[4], y[5], y[6], y[7]);
    reinterpret_cast<float4*>(&yp[row * 64 + jb])[0] = w0;
    reinterpret_cast<float4*>(&yp[row * 64 + jb])[1] = w1;
    if (o == 0) {
        g_pm[slot * 64 + row] = m;
        g_pl[slot * 64 + row] = l;
    }
}

// ---------------------------------------------------------------------------
// Kernel 2b: combine partials -> g_y
// grid = (16, 8), 256 threads
// ---------------------------------------------------------------------------
__global__ __launch_bounds__(256) void combine_kernel()
{
    const int tau = blockIdx.x;
    const int b = blockIdx.y;
    const int nch = (tau >> 1) + 1;   // ceil((tau+1)/2)
    const int tid = threadIdx.x;
    const int row = tid >> 2;
    const int cq = tid & 3;
    const int cb = cq * 16;

    const int slot0 = (b * 16 + tau) * 8;

    float mv[8], lv[8];
    float M = -1e30f;
    for (int k = 0; k < nch; ++k) {
        mv[k] = g_pm[(slot0 + k) * 64 + row];
        lv[k] = g_pl[(slot0 + k) * 64 + row];
        M = fmaxf(M, mv[k]);
    }
    float L = 0.f;
    float wgt[8];
    for (int k = 0; k < nch; ++k) {
        wgt[k] = __expf(mv[k] - M);
        L += lv[k] * wgt[k];
    }

    float acc[16] = {};
    for (int k = 0; k < nch; ++k) {
        const float* yp = g_py + (size_t)(slot0 + k) * 4096 + row * 64 + cb;
        float wk = wgt[k];
        #pragma unroll
        for (int q = 0; q < 4; ++q) {
            float4 v = reinterpret_cast<const float4*>(yp)[q];
            acc[q * 4 + 0] += wk * v.x; acc[q * 4 + 1] += wk * v.y;
            acc[q * 4 + 2] += wk * v.z; acc[q * 4 + 3] += wk * v.w;
        }
    }
    float inv = 1.0f / L;
    float* yb = g_y + ((size_t)b * TT + tau * 64 + row) * CC + cb;
    #pragma unroll
    for (int q = 0; q < 4; ++q) {
        float4 v = make_float4(acc[q * 4 + 0] * inv, acc[q * 4 + 1] * inv,
                               acc[q * 4 + 2] * inv, acc[q * 4 + 3] * inv);
        reinterpret_cast<float4*>(yb)[q] = v;
    }
}

// ---------------------------------------------------------------------------
// Kernel 3: out = y @ Wproj^T + bproj  (32-row tiles)
// ---------------------------------------------------------------------------
__global__ __launch_bounds__(256) void proj_kernel(
    const float* __restrict__ W, const float* __restrict__ bias,
    float* __restrict__ out)
{
    __shared__ float Xs[32][65];
    __shared__ float Ws[64][65];
    const int row0 = blockIdx.x * 32;
    const int tid = threadIdx.x;
    const int tx = tid & 15, ty = tid >> 4;
    const int i0 = ty * 2, j0 = tx * 4;

    for (int k = tid; k < 32 * 16; k += 256) {
        int r = k >> 4, c4 = k & 15;
        float4 xv = reinterpret_cast<const float4*>(g_y + (size_t)(row0 + r) * CC)[c4];
        Xs[r][c4 * 4 + 0] = xv.x; Xs[r][c4 * 4 + 1] = xv.y;
        Xs[r][c4 * 4 + 2] = xv.z; Xs[r][c4 * 4 + 3] = xv.w;
    }
    for (int k = tid; k < 64 * 16; k += 256) {
        int r = k >> 4, c4 = k & 15;
        float4 wv = reinterpret_cast<const float4*>(W + (size_t)r * CC)[c4];
        Ws[r][c4 * 4 + 0] = wv.x; Ws[r][c4 * 4 + 1] = wv.y;
        Ws[r][c4 * 4 + 2] = wv.z; Ws[r][c4 * 4 + 3] = wv.w;
    }
    __syncthreads();

    float acc[2][4] = {};
    #pragma unroll
    for (int c = 0; c < 64; ++c) {
        float xr[2], wr[4];
        #pragma unroll
        for (int i = 0; i < 2; ++i) xr[i] = Xs[i0 + i][c];
        #pragma unroll
        for (int j = 0; j < 4; ++j) wr[j] = Ws[j0 + j][c];
        #pragma unroll
        for (int i = 0; i < 2; ++i)
            #pragma unroll
            for (int j = 0; j < 4; ++j)
                acc[i][j] = fmaf(xr[i], wr[j], acc[i][j]);
    }
    #pragma unroll
    for (int i = 0; i < 2; ++i)
        #pragma unroll
        for (int j = 0; j < 4; ++j)
            out[(size_t)(row0 + i0 + i) * CC + j0 + j] = acc[i][j] + bias[j0 + j];
}

// ---------------------------------------------------------------------------
extern "C" void kernel_launch(void* const* d_in, const int* in_sizes, int n_in,
                              void* d_out, int out_size)
{
    const float* x     = (const float*)d_in[0];
    const float* Wqkv  = (const float*)d_in[1];
    const float* bqkv  = (const float*)d_in[2];
    const float* embk  = (const float*)d_in[3];
    const float* embv  = (const float*)d_in[4];
    const float* Wproj = (const float*)d_in[5];
    const float* bproj = (const float*)d_in[6];
    float* out = (float*)d_out;

    (void)in_sizes; (void)n_in; (void)out_size;

    cudaFuncSetAttribute(attn_partial_kernel,
                         cudaFuncAttributeMaxDynamicSharedMemorySize,
                         (int)sizeof(AttnSmem));

    qkv_kernel<<<dim3(BB * TT / 32, 3), 256>>>(x, Wqkv, bqkv);
    attn_partial_kernel<<<dim3(72, BB), 512, sizeof(AttnSmem)>>>(embk, embv);
    combine_kernel<<<dim3(16, BB), 256>>>();
    proj_kernel<<<BB * TT / 32, 256>>>(Wproj, bproj, out);
}

// round 10
// speedup vs baseline: 5.3609x; 2.2857x over previous
#include <cuda_runtime.h>
#include <cuda_fp16.h>
#include <mma.h>
#include <math.h>

using namespace nvcuda;

#define BB 8
#define TT 1024
#define CC 64
#define LDH 72     // half leading dim (mult of 8)
#define LD2H 136   // half leading dim for 128-col Pd
#define LDF 72     // f32 leading dim
#define LD2F 136   // f32 leading dim for 128-col S2

// ---- device scratch (half precision operand tensors) ----
__device__ __align__(16) __half g_qh[BB*TT*CC];
__device__ __align__(16) __half g_kh[BB*TT*CC];
__device__ __align__(16) __half g_vh[BB*TT*CC];
__device__ __align__(16) __half g_ekh[TT*CC];
__device__ __align__(16) __half g_evh[TT*CC];

// split-softmax partial state: slot = ((b*16 + tau)*8 + kappa)
__device__ float g_pm[BB*16*8*64];
__device__ float g_pl[BB*16*8*64];
__device__ float g_py[(size_t)BB*16*8*64*64];

// Job table: value = tau*16 + kappa. Chunk = 2 s-tiles. Ordered big-jobs-first.
__device__ const int c_jobs[72] = {
    240,241,242,243,244,245,246,247,
    224,225,226,227,228,229,230,
    208,209,210,211,212,213,214,
    192,193,194,195,196,197,
    176,177,178,179,180,181,
    160,161,162,163,164,
    144,145,146,147,148,
    128,129,130,131,
    112,113,114,115,
    96,97,98,
    80,81,82,
    64,65,
    48,49,
    32,
    16,
    231,198,165,132,99,66,33,0
};

// ---------------------------------------------------------------------------
// Kernel 1: qkv = x @ Wqkv^T + bqkv -> g_qh/g_kh/g_vh (half)
//           chunk 3 converts embk/embv -> g_ekh/g_evh
// grid = (256, 4), 256 threads
// ---------------------------------------------------------------------------
__global__ __launch_bounds__(256) void qkv_kernel(
    const float* __restrict__ x, const float* __restrict__ W,
    const float* __restrict__ bias,
    const float* __restrict__ embk, const float* __restrict__ embv)
{
    const int chunk = blockIdx.y;
    const int tid = threadIdx.x;

    if (chunk == 3) {
        // convert emb tables to half: 256 blocks x 256 threads x 1 float2
        int g = blockIdx.x * 256 + tid;           // 0..65535
        const int half_n = TT * CC / 2;           // 32768 float2 per table
        if (g < half_n) {
            float2 a = reinterpret_cast<const float2*>(embk)[g];
            reinterpret_cast<__half2*>(g_ekh)[g] = __floats2half2_rn(a.x, a.y);
        } else {
            int gg = g - half_n;
            float2 a = reinterpret_cast<const float2*>(embv)[gg];
            reinterpret_cast<__half2*>(g_evh)[gg] = __floats2half2_rn(a.x, a.y);
        }
        return;
    }

    __shared__ float Xs[32][65];
    __shared__ float Ws[64][65];
    const int row0 = blockIdx.x * 32;
    const int tx = tid & 15, ty = tid >> 4;
    const int i0 = ty * 2, j0 = tx * 4;

    for (int k = tid; k < 32 * 16; k += 256) {
        int r = k >> 4, c4 = k & 15;
        float4 v = reinterpret_cast<const float4*>(x + (size_t)(row0 + r) * CC)[c4];
        Xs[r][c4 * 4 + 0] = v.x; Xs[r][c4 * 4 + 1] = v.y;
        Xs[r][c4 * 4 + 2] = v.z; Xs[r][c4 * 4 + 3] = v.w;
    }
    for (int k = tid; k < 64 * 16; k += 256) {
        int r = k >> 4, c4 = k & 15;
        float4 w = reinterpret_cast<const float4*>(W + (size_t)(chunk * 64 + r) * CC)[c4];
        Ws[r][c4 * 4 + 0] = w.x; Ws[r][c4 * 4 + 1] = w.y;
        Ws[r][c4 * 4 + 2] = w.z; Ws[r][c4 * 4 + 3] = w.w;
    }
    __syncthreads();

    float acc[2][4] = {};
    #pragma unroll
    for (int c = 0; c < 64; ++c) {
        float xr[2], wr[4];
        #pragma unroll
        for (int i = 0; i < 2; ++i) xr[i] = Xs[i0 + i][c];
        #pragma unroll
        for (int j = 0; j < 4; ++j) wr[j] = Ws[j0 + j][c];
        #pragma unroll
        for (int i = 0; i < 2; ++i)
            #pragma unroll
            for (int j = 0; j < 4; ++j)
                acc[i][j] = fmaf(xr[i], wr[j], acc[i][j]);
    }
    __half* out = (chunk == 0) ? g_qh : (chunk == 1) ? g_kh : g_vh;
    #pragma unroll
    for (int i = 0; i < 2; ++i) {
        float v0 = acc[i][0] + bias[chunk * 64 + j0 + 0];
        float v1 = acc[i][1] + bias[chunk * 64 + j0 + 1];
        float v2 = acc[i][2] + bias[chunk * 64 + j0 + 2];
        float v3 = acc[i][3] + bias[chunk * 64 + j0 + 3];
        __half2* dst = reinterpret_cast<__half2*>(&out[(size_t)(row0 + i0 + i) * CC + j0]);
        dst[0] = __floats2half2_rn(v0, v1);
        dst[1] = __floats2half2_rn(v2, v3);
    }
}

// ---------------------------------------------------------------------------
// Kernel 2: partial flash attention, fp16 wmma m16n16k16, fp32 accum
// grid = (72 jobs, 8 batch), 512 threads (16 warps)
// ---------------------------------------------------------------------------
struct alignas(16) AttnSmem {
    __half Qh[64 * LDH];
    __half Kh[128 * LDH];
    __half Vh[128 * LDH];
    __half Ekh[192 * LDH];
    __half Evh[192 * LDH];
    __half Ph[64 * LDH];
    __half Pdh[64 * LD2H];
    float  S1f[64 * LDF];    // S1 scores, then Yd (phase 2 output)
    float  S2f[64 * LD2F];   // S2 scores
};

typedef wmma::fragment<wmma::matrix_a, 16, 16, 16, __half, wmma::row_major> HA;
typedef wmma::fragment<wmma::matrix_b, 16, 16, 16, __half, wmma::col_major> HBc;
typedef wmma::fragment<wmma::matrix_b, 16, 16, 16, __half, wmma::row_major> HBr;
typedef wmma::fragment<wmma::accumulator, 16, 16, 16, float> HC;

__global__ __launch_bounds__(512, 1) void attn_partial_kernel()
{
    extern __shared__ char smem_raw[];
    AttnSmem& sm = *reinterpret_cast<AttnSmem*>(smem_raw);

    const int b = blockIdx.y;
    const int job = c_jobs[blockIdx.x];
    const int tau = job >> 4;
    const int kap = job & 15;
    const int t0 = tau * 64;
    const int stile0 = kap * 2;
    const int ns = min(2, tau + 1 - 2 * kap);

    const int tid = threadIdx.x;
    const int w = tid >> 5;

    // softmax / Y-ownership mapping: 8 threads per row, 8 cols each
    const int row = tid >> 3;
    const int oo = tid & 7;
    const int jb = oo * 8;

    // ---- stage everything once per job ----
    {
        // Q: 64 rows
        const uint4* qg = reinterpret_cast<const uint4*>(g_qh + ((size_t)b * TT + t0) * CC);
        uint4* qs = reinterpret_cast<uint4*>(sm.Qh);
        for (int k = tid; k < 64 * 8; k += 512) {
            int r = k >> 3, c = k & 7;
            qs[r * 9 + c] = qg[r * 8 + c];
        }
        // K, V: ns*64 rows
        const int s0b = stile0 * 64;
        const uint4* kg = reinterpret_cast<const uint4*>(g_kh + ((size_t)b * TT + s0b) * CC);
        const uint4* vg = reinterpret_cast<const uint4*>(g_vh + ((size_t)b * TT + s0b) * CC);
        uint4* ks = reinterpret_cast<uint4*>(sm.Kh);
        uint4* vs = reinterpret_cast<uint4*>(sm.Vh);
        for (int k = tid; k < ns * 64 * 8; k += 512) {
            int r = k >> 3, c = k & 7;
            ks[r * 9 + c] = kg[r * 8 + c];
            vs[r * 9 + c] = vg[r * 8 + c];
        }
        // Ek/Ev merged window: rows [base, base+nrows)
        const int nrows = 64 * (ns - 1) + 128;
        const int base = t0 - (stile0 + ns - 1) * 64 - 63;
        const uint4* eg = reinterpret_cast<const uint4*>(g_ekh);
        const uint4* vg2 = reinterpret_cast<const uint4*>(g_evh);
        uint4* es = reinterpret_cast<uint4*>(sm.Ekh);
        uint4* vs2 = reinterpret_cast<uint4*>(sm.Evh);
        for (int k = tid; k < nrows * 8; k += 512) {
            int r = k >> 3, c = k & 7;
            int e = base + r;
            e = (e < 0) ? 0 : (e > TT - 1 ? TT - 1 : e);
            es[r * 9 + c] = eg[e * 8 + c];
            vs2[r * 9 + c] = vg2[e * 8 + c];
        }
    }
    __syncthreads();

    float m = -1e30f, l = 0.f;
    float y[8] = {};

    for (int it = 0; it < ns; ++it) {
        const int s0 = (stile0 + it) * 64;
        const int offset = 64 * (ns - 1 - it);   // Ek/Ev window row offset

        // ---- GEMM 1: S1 = Q K^T (4 tiles) + S2 band (5 tiles) per row-tile ----
        {
            const int rt = w >> 2;
            const int q = ((w & 3) + rt) & 3;    // rotate imbalance across SMSPs
            HA aq[4];
            #pragma unroll
            for (int k0 = 0; k0 < 4; ++k0)
                wmma::load_matrix_sync(aq[k0], &sm.Qh[rt * 16 * LDH + k0 * 16], LDH);

            for (int t = q; t < 9; t += 4) {
                HC c; wmma::fill_fragment(c, 0.f);
                if (t < 4) {
                    #pragma unroll
                    for (int k0 = 0; k0 < 4; ++k0) {
                        HBc bk;
                        wmma::load_matrix_sync(bk,
                            &sm.Kh[(it * 64 + t * 16) * LDH + k0 * 16], LDH);
                        wmma::mma_sync(c, aq[k0], bk, c);
                    }
                    wmma::store_matrix_sync(&sm.S1f[rt * 16 * LDF + t * 16], c, LDF,
                                            wmma::mem_row_major);
                } else {
                    const int ce = rt + (t - 4);
                    #pragma unroll
                    for (int k0 = 0; k0 < 4; ++k0) {
                        HBc be;
                        wmma::load_matrix_sync(be,
                            &sm.Ekh[(offset + ce * 16) * LDH + k0 * 16], LDH);
                        wmma::mma_sync(c, aq[k0], be, c);
                    }
                    wmma::store_matrix_sync(&sm.S2f[rt * 16 * LD2F + ce * 16], c, LD2F,
                                            wmma::mem_row_major);
                }
            }
        }
        __syncthreads();

        // ---- softmax: combine S1 + S2(diag band), mask, online update ----
        float alpha;
        {
            float sv[8];
            float mt = -1e30f;
            #pragma unroll
            for (int jj = 0; jj < 8; ++jj) {
                int j = jb + jj;
                int dd = row - j + 63;                       // band col in [row, row+63]
                float s = (sm.S1f[row * LDF + j] + sm.S2f[row * LD2F + dd]) * 0.125f;
                if (s0 + j > t0 + row) s = -1e30f;
                sv[jj] = s;
                mt = fmaxf(mt, s);
            }
            mt = fmaxf(mt, __shfl_xor_sync(0xffffffffu, mt, 1));
            mt = fmaxf(mt, __shfl_xor_sync(0xffffffffu, mt, 2));
            mt = fmaxf(mt, __shfl_xor_sync(0xffffffffu, mt, 4));
            float mnew = fmaxf(m, mt);
            alpha = __expf(m - mnew);
            m = mnew;
            float ps = 0.f;
            #pragma unroll
            for (int jj = 0; jj < 8; ++jj) {
                int j = jb + jj;
                float p = __expf(sv[jj] - mnew);
                ps += p;
                sm.Ph[row * LDH + j] = __float2half(p);
                sm.Pdh[row * LD2H + (row - j + 63)] = __float2half(p);
            }
            // zero complement of the band (mod-128 trick covers all read tiles)
            #pragma unroll
            for (int jj = 0; jj < 8; ++jj) {
                int z = (row + 64 + jb + jj) & 127;
                sm.Pdh[row * LD2H + z] = __float2half(0.f);
            }
            ps += __shfl_xor_sync(0xffffffffu, ps, 1);
            ps += __shfl_xor_sync(0xffffffffu, ps, 2);
            ps += __shfl_xor_sync(0xffffffffu, ps, 4);
            l = l * alpha + ps;
        }
        __syncthreads();

        // ---- GEMM 2: Yd = P V + Pd Ev (band K-tiles only), store to S1f ----
        {
            const int rt = w >> 2, ct = w & 3;
            HC c; wmma::fill_fragment(c, 0.f);
            #pragma unroll
            for (int k0 = 0; k0 < 4; ++k0) {
                HA pa;
                wmma::load_matrix_sync(pa, &sm.Ph[rt * 16 * LDH + k0 * 16], LDH);
                HBr bv;
                wmma::load_matrix_sync(bv,
                    &sm.Vh[(it * 64 + k0 * 16) * LDH + ct * 16], LDH);
                wmma::mma_sync(c, pa, bv, c);
            }
            #pragma unroll
            for (int kk = 0; kk < 5; ++kk) {
                const int k0 = rt + kk;                      // band: k0 in [rt, rt+4]
                HA pd;
                wmma::load_matrix_sync(pd, &sm.Pdh[rt * 16 * LD2H + k0 * 16], LD2H);
                HBr be;
                wmma::load_matrix_sync(be,
                    &sm.Evh[(offset + k0 * 16) * LDH + ct * 16], LDH);
                wmma::mma_sync(c, pd, be, c);
            }
            wmma::store_matrix_sync(&sm.S1f[rt * 16 * LDF + ct * 16], c, LDF,
                                    wmma::mem_row_major);
        }
        __syncthreads();

        // ---- rescale-and-accumulate in registers ----
        {
            float4 d0 = *reinterpret_cast<float4*>(&sm.S1f[row * LDF + jb]);
            float4 d1 = *reinterpret_cast<float4*>(&sm.S1f[row * LDF + jb + 4]);
            y[0] = y[0] * alpha + d0.x; y[1] = y[1] * alpha + d0.y;
            y[2] = y[2] * alpha + d0.z; y[3] = y[3] * alpha + d0.w;
            y[4] = y[4] * alpha + d1.x; y[5] = y[5] * alpha + d1.y;
            y[6] = y[6] * alpha + d1.z; y[7] = y[7] * alpha + d1.w;
        }
        __syncthreads();   // S1f reads done before next iter's GEMM1 overwrites
    }

    // ---- write partial state ----
    const int slot = (b * 16 + tau) * 8 + kap;
    float* yp = g_py + (size_t)slot * 4096;
    reinterpret_cast<float4*>(&yp[row * 64 + jb])[0] = make_float4(y[0], y[1], y[2], y[3]);
    reinterpret_cast<float4*>(&yp[row * 64 + jb])[1] = make_float4(y[4], y[5], y[6], y[7]);
    if (oo == 0) {
        g_pm[slot * 64 + row] = m;
        g_pl[slot * 64 + row] = l;
    }
}

// ---------------------------------------------------------------------------
// Kernel 3: combine partials + output projection (fused)
// grid = (16, 8), 256 threads
// ---------------------------------------------------------------------------
__global__ __launch_bounds__(256) void combine_proj_kernel(
    const float* __restrict__ W, const float* __restrict__ bias,
    float* __restrict__ out)
{
    __shared__ float Ys[64][65];
    __shared__ float Ws[64][65];

    const int tau = blockIdx.x;
    const int b = blockIdx.y;
    const int nch = (tau >> 1) + 1;
    const int tid = threadIdx.x;

    // stage Wproj
    for (int k = tid; k < 64 * 16; k += 256) {
        int r = k >> 4, c4 = k & 15;
        float4 wv = reinterpret_cast<const float4*>(W + (size_t)r * CC)[c4];
        Ws[r][c4 * 4 + 0] = wv.x; Ws[r][c4 * 4 + 1] = wv.y;
        Ws[r][c4 * 4 + 2] = wv.z; Ws[r][c4 * 4 + 3] = wv.w;
    }

    // combine phase: 4 threads per row, 16 cols each
    {
        const int row = tid >> 2;
        const int cq = tid & 3;
        const int cb = cq * 16;
        const int slot0 = (b * 16 + tau) * 8;

        float mv[8], lv[8];
        float M = -1e30f;
        for (int k = 0; k < nch; ++k) {
            mv[k] = g_pm[(slot0 + k) * 64 + row];
            lv[k] = g_pl[(slot0 + k) * 64 + row];
            M = fmaxf(M, mv[k]);
        }
        float L = 0.f;
        float wgt[8];
        for (int k = 0; k < nch; ++k) {
            wgt[k] = __expf(mv[k] - M);
            L += lv[k] * wgt[k];
        }
        float acc[16] = {};
        for (int k = 0; k < nch; ++k) {
            const float* yp = g_py + (size_t)(slot0 + k) * 4096 + row * 64 + cb;
            float wk = wgt[k];
            #pragma unroll
            for (int q = 0; q < 4; ++q) {
                float4 v = reinterpret_cast<const float4*>(yp)[q];
                acc[q * 4 + 0] += wk * v.x; acc[q * 4 + 1] += wk * v.y;
                acc[q * 4 + 2] += wk * v.z; acc[q * 4 + 3] += wk * v.w;
            }
        }
        float inv = 1.0f / L;
        #pragma unroll
        for (int q = 0; q < 16; ++q)
            Ys[row][cb + q] = acc[q] * inv;
    }
    __syncthreads();

    // projection phase: 16x16 threads, 4x4 microtile
    {
        const int tx = tid & 15, ty = tid >> 4;
        const int i0 = ty * 4, j0 = tx * 4;
        float acc[4][4] = {};
        #pragma unroll
        for (int c = 0; c < 64; ++c) {
            float xr[4], wr[4];
            #pragma unroll
            for (int i = 0; i < 4; ++i) xr[i] = Ys[i0 + i][c];
            #pragma unroll
            for (int j = 0; j < 4; ++j) wr[j] = Ws[j0 + j][c];
            #pragma unroll
            for (int i = 0; i < 4; ++i)
                #pragma unroll
                for (int j = 0; j < 4; ++j)
                    acc[i][j] = fmaf(xr[i], wr[j], acc[i][j]);
        }
        float* ob = out + ((size_t)b * TT + tau * 64) * CC;
        #pragma unroll
        for (int i = 0; i < 4; ++i)
            #pragma unroll
            for (int j = 0; j < 4; ++j)
                ob[(size_t)(i0 + i) * CC + j0 + j] = acc[i][j] + bias[j0 + j];
    }
}

// ---------------------------------------------------------------------------
extern "C" void kernel_launch(void* const* d_in, const int* in_sizes, int n_in,
                              void* d_out, int out_size)
{
    const float* x     = (const float*)d_in[0];
    const float* Wqkv  = (const float*)d_in[1];
    const float* bqkv  = (const float*)d_in[2];
    const float* embk  = (const float*)d_in[3];
    const float* embv  = (const float*)d_in[4];
    const float* Wproj = (const float*)d_in[5];
    const float* bproj = (const float*)d_in[6];
    float* out = (float*)d_out;

    (void)in_sizes; (void)n_in; (void)out_size;

    cudaFuncSetAttribute(attn_partial_kernel,
                         cudaFuncAttributeMaxDynamicSharedMemorySize,
                         (int)sizeof(AttnSmem));

    qkv_kernel<<<dim3(BB * TT / 32, 4), 256>>>(x, Wqkv, bqkv, embk, embv);
    attn_partial_kernel<<<dim3(72, BB), 512, sizeof(AttnSmem)>>>();
    combine_proj_kernel<<<dim3(16, BB), 256>>>(Wproj, bproj, out);
}

// round 13
// speedup vs baseline: 6.2086x; 1.1581x over previous
#include <cuda_runtime.h>
#include <cuda_fp16.h>
#include <mma.h>
#include <math.h>

using namespace nvcuda;

#define BB 8
#define TT 1024
#define CC 64
#define LDH 72     // half leading dim (mult of 8)
#define LDPD 80    // compressed Pd leading dim (half)
#define LDS1 68    // S1 f32 leading dim (mult of 4)
#define LDS2 80    // compressed S2 f32 leading dim (mult of 4)

// ---- device scratch (zero-initialized at module load) ----
__device__ __align__(16) __half g_qh[BB*TT*CC];
__device__ __align__(16) __half g_kh[BB*TT*CC];
__device__ __align__(16) __half g_vh[BB*TT*CC];
__device__ __align__(16) __half g_ekh[TT*CC];
__device__ __align__(16) __half g_evh[TT*CC];

// split-softmax partials: slot = (b*16 + tau)*16 + kap  (16 kap slots; unused stay 0)
__device__ float g_pm[BB*16*16*64];
__device__ float g_pl[BB*16*16*64];
__device__ float g_py[(size_t)BB*16*16*64*64];

// uniform job table: value = tau*16 + kap, one s-tile per job (136 jobs/batch)
__device__ const int c_jt[136] = {
    0,
    16,17,
    32,33,34,
    48,49,50,51,
    64,65,66,67,68,
    80,81,82,83,84,85,
    96,97,98,99,100,101,102,
    112,113,114,115,116,117,118,119,
    128,129,130,131,132,133,134,135,136,
    144,145,146,147,148,149,150,151,152,153,
    160,161,162,163,164,165,166,167,168,169,170,
    176,177,178,179,180,181,182,183,184,185,186,187,
    192,193,194,195,196,197,198,199,200,201,202,203,204,
    208,209,210,211,212,213,214,215,216,217,218,219,220,221,
    224,225,226,227,228,229,230,231,232,233,234,235,236,237,238,
    240,241,242,243,244,245,246,247,248,249,250,251,252,253,254,255
};

typedef wmma::fragment<wmma::matrix_a, 16, 16, 16, __half, wmma::row_major> HA;
typedef wmma::fragment<wmma::matrix_b, 16, 16, 16, __half, wmma::col_major> HBc;
typedef wmma::fragment<wmma::matrix_b, 16, 16, 16, __half, wmma::row_major> HBr;
typedef wmma::fragment<wmma::accumulator, 16, 16, 16, float> HC;

// ---------------------------------------------------------------------------
// Kernel 1: qkv = x @ Wqkv^T + bqkv -> g_qh/g_kh/g_vh (half), fp16 wmma.
// Blocks [0,128): 64-row GEMM tiles. Blocks [128,160): emb f32->half convert.
// 256 threads (8 warps).
// ---------------------------------------------------------------------------
struct alignas(16) QkvSmem {
    __half Xh[64 * LDH];      // 9216 B
    __half Wh[192 * LDH];     // 27648 B
    float  Of[64 * 196];      // 50176 B
};

__global__ __launch_bounds__(256, 2) void qkv_kernel(
    const float* __restrict__ x, const float* __restrict__ W,
    const float* __restrict__ bias,
    const float* __restrict__ embk, const float* __restrict__ embv)
{
    const int tid = threadIdx.x;

    if (blockIdx.x >= 128) {
        // emb conversion: 32 blocks x 256 threads x 4 half2 per table
        int g = (blockIdx.x - 128) * 256 + tid;      // 0..8191
        #pragma unroll
        for (int kk = 0; kk < 4; ++kk) {
            int i = g + kk * 8192;                   // 0..32767
            float2 a = reinterpret_cast<const float2*>(embk)[i];
            reinterpret_cast<__half2*>(g_ekh)[i] = __floats2half2_rn(a.x, a.y);
            float2 b = reinterpret_cast<const float2*>(embv)[i];
            reinterpret_cast<__half2*>(g_evh)[i] = __floats2half2_rn(b.x, b.y);
        }
        return;
    }

    extern __shared__ char smem_raw[];
    QkvSmem& sm = *reinterpret_cast<QkvSmem*>(smem_raw);
    const int row0 = blockIdx.x * 64;
    const int w = tid >> 5;

    // stage x tile (64x64) as half
    for (int k = tid; k < 64 * 16; k += 256) {
        int r = k >> 4, c4 = k & 15;
        float4 v = reinterpret_cast<const float4*>(x + (size_t)(row0 + r) * CC)[c4];
        __half2* dst = reinterpret_cast<__half2*>(&sm.Xh[r * LDH + c4 * 4]);
        dst[0] = __floats2half2_rn(v.x, v.y);
        dst[1] = __floats2half2_rn(v.z, v.w);
    }
    // stage W (192x64) as half
    for (int k = tid; k < 192 * 16; k += 256) {
        int r = k >> 4, c4 = k & 15;
        float4 v = reinterpret_cast<const float4*>(W + (size_t)r * CC)[c4];
        __half2* dst = reinterpret_cast<__half2*>(&sm.Wh[r * LDH + c4 * 4]);
        dst[0] = __floats2half2_rn(v.x, v.y);
        dst[1] = __floats2half2_rn(v.z, v.w);
    }
    __syncthreads();

    // 48 tiles (4 rt x 12 ct), warp w does rt = w&3, ct = (w>>2) + 2i
    {
        const int rt = w & 3;
        HA ax[4];
        #pragma unroll
        for (int k0 = 0; k0 < 4; ++k0)
            wmma::load_matrix_sync(ax[k0], &sm.Xh[rt * 16 * LDH + k0 * 16], LDH);
        #pragma unroll
        for (int i = 0; i < 6; ++i) {
            const int ct = (w >> 2) + 2 * i;
            HC c; wmma::fill_fragment(c, 0.f);
            #pragma unroll
            for (int k0 = 0; k0 < 4; ++k0) {
                HBc bw;   // B[k=c][n] = W[n][c] -> col-major
                wmma::load_matrix_sync(bw, &sm.Wh[ct * 16 * LDH + k0 * 16], LDH);
                wmma::mma_sync(c, ax[k0], bw, c);
            }
            wmma::store_matrix_sync(&sm.Of[rt * 16 * 196 + ct * 16], c, 196,
                                    wmma::mem_row_major);
        }
    }
    __syncthreads();

    // write out: bias add + convert to half, split into q/k/v
    for (int k = tid; k < 64 * 96; k += 256) {
        int r = k / 96, hc = k % 96;
        int ch = hc >> 5, cc = (hc & 31) * 2;
        float v0 = sm.Of[r * 196 + ch * 64 + cc]     + bias[ch * 64 + cc];
        float v1 = sm.Of[r * 196 + ch * 64 + cc + 1] + bias[ch * 64 + cc + 1];
        __half* outp = (ch == 0) ? g_qh : (ch == 1) ? g_kh : g_vh;
        *reinterpret_cast<__half2*>(&outp[(size_t)(row0 + r) * CC + cc]) =
            __floats2half2_rn(v0, v1);
    }
}

// ---------------------------------------------------------------------------
// Kernel 2: single-s-tile partial attention job, fp16 wmma, occupancy 2.
// grid = (136, 8), 512 threads (16 warps). Smem 110 KB.
// ---------------------------------------------------------------------------
struct alignas(16) AttnSmem {
    __half Qh[64 * LDH];      // 9216  (aliased as Ph after GEMM1)
    __half Kh[64 * LDH];      // 9216
    __half Vh[64 * LDH];      // 9216
    __half Ekh[128 * LDH];    // 18432
    __half Evh[128 * LDH];    // 18432
    __half Pdh[64 * LDPD];    // 10240 (band-compressed Pd)
    float  S1f[64 * LDS1];    // 17408
    float  S2f[64 * LDS2];    // 20480 (band-compressed S2)
};  // total 112640 B

__global__ __launch_bounds__(512, 2) void attn_partial_kernel()
{
    extern __shared__ char smem_raw[];
    AttnSmem& sm = *reinterpret_cast<AttnSmem*>(smem_raw);

    const int b = blockIdx.y;
    const int job = c_jt[blockIdx.x];
    const int tau = job >> 4;
    const int kap = job & 15;
    const int t0 = tau * 64;
    const int s0 = kap * 64;
    const int D = t0 - s0;                 // >= 0

    const int tid = threadIdx.x;
    const int w = tid >> 5;

    // softmax mapping: 8 threads per row, 8 cols each
    const int row = tid >> 3;
    const int oo = tid & 7;
    const int jb = oo * 8;
    const int rr = row & 15;               // row within its 16-row tile

    // ---- stage Q, K, V (64 rows each) and Ek/Ev windows (128 rows) ----
    {
        const uint4* qg = reinterpret_cast<const uint4*>(g_qh + ((size_t)b * TT + t0) * CC);
        const uint4* kg = reinterpret_cast<const uint4*>(g_kh + ((size_t)b * TT + s0) * CC);
        const uint4* vg = reinterpret_cast<const uint4*>(g_vh + ((size_t)b * TT + s0) * CC);
        uint4* qs = reinterpret_cast<uint4*>(sm.Qh);
        uint4* ks = reinterpret_cast<uint4*>(sm.Kh);
        uint4* vs = reinterpret_cast<uint4*>(sm.Vh);
        {
            int r = tid >> 3, c = tid & 7;          // exactly 512 items
            qs[r * 9 + c] = qg[r * 8 + c];
            ks[r * 9 + c] = kg[r * 8 + c];
            vs[r * 9 + c] = vg[r * 8 + c];
        }
        const int base = D - 63;
        const uint4* eg = reinterpret_cast<const uint4*>(g_ekh);
        const uint4* vg2 = reinterpret_cast<const uint4*>(g_evh);
        uint4* es = reinterpret_cast<uint4*>(sm.Ekh);
        uint4* vs2 = reinterpret_cast<uint4*>(sm.Evh);
        #pragma unroll
        for (int kk = 0; kk < 2; ++kk) {
            int k = tid + kk * 512;
            int r = k >> 3, c = k & 7;
            int e = base + r;
            e = (e < 0) ? 0 : (e > TT - 1 ? TT - 1 : e);
            es[r * 9 + c] = eg[e * 8 + c];
            vs2[r * 9 + c] = vg2[e * 8 + c];
        }
    }
    __syncthreads();

    // ---- GEMM 1: S1 = Q K^T (4 tiles/rt) + S2 band (5 tiles/rt), 9 per rt ----
    {
        const int rt = w >> 2;
        const int q = ((w & 3) + rt) & 3;
        HA aq[4];
        #pragma unroll
        for (int k0 = 0; k0 < 4; ++k0)
            wmma::load_matrix_sync(aq[k0], &sm.Qh[rt * 16 * LDH + k0 * 16], LDH);

        for (int t = q; t < 9; t += 4) {
            HC c; wmma::fill_fragment(c, 0.f);
            if (t < 4) {
                #pragma unroll
                for (int k0 = 0; k0 < 4; ++k0) {
                    HBc bk;
                    wmma::load_matrix_sync(bk, &sm.Kh[t * 16 * LDH + k0 * 16], LDH);
                    wmma::mma_sync(c, aq[k0], bk, c);
                }
                wmma::store_matrix_sync(&sm.S1f[rt * 16 * LDS1 + t * 16], c, LDS1,
                                        wmma::mem_row_major);
            } else {
                const int ce = rt + (t - 4);            // band col-tile in [rt, rt+4]
                #pragma unroll
                for (int k0 = 0; k0 < 4; ++k0) {
                    HBc be;
                    wmma::load_matrix_sync(be, &sm.Ekh[ce * 16 * LDH + k0 * 16], LDH);
                    wmma::mma_sync(c, aq[k0], be, c);
                }
                wmma::store_matrix_sync(&sm.S2f[rt * 16 * LDS2 + (ce - rt) * 16], c,
                                        LDS2, wmma::mem_row_major);
            }
        }
    }
    __syncthreads();

    // ---- softmax (single s-tile: m = max, l = sum); write P (into Qh) + Pd ----
    {
        float sv[8];
        float mt = -1e30f;
        #pragma unroll
        for (int jj = 0; jj < 8; ++jj) {
            int j = jb + jj;
            int c2 = rr + 63 - j;                       // compressed S2 col in [rr, rr+63]
            float s = (sm.S1f[row * LDS1 + j] + sm.S2f[row * LDS2 + c2]) * 0.125f;
            if (j > D + row) s = -1e30f;                // causal mask
            sv[jj] = s;
            mt = fmaxf(mt, s);
        }
        mt = fmaxf(mt, __shfl_xor_sync(0xffffffffu, mt, 1));
        mt = fmaxf(mt, __shfl_xor_sync(0xffffffffu, mt, 2));
        mt = fmaxf(mt, __shfl_xor_sync(0xffffffffu, mt, 4));
        float ps = 0.f;
        #pragma unroll
        for (int jj = 0; jj < 8; ++jj) {
            int j = jb + jj;
            float p = __expf(sv[jj] - mt);
            ps += p;
            sm.Qh[row * LDH + j] = __float2half(p);            // P (aliases dead Qh)
            sm.Pdh[row * LDPD + (rr + 63 - j)] = __float2half(p); // band [rr, rr+63]
        }
        // zero band complement: cols (rr+64+k) % 80 for k in [0,16), 2 per thread
        #pragma unroll
        for (int kz = 0; kz < 2; ++kz) {
            int z = (rr + 64 + oo * 2 + kz) % 80;
            sm.Pdh[row * LDPD + z] = __float2half(0.f);
        }
        ps += __shfl_xor_sync(0xffffffffu, ps, 1);
        ps += __shfl_xor_sync(0xffffffffu, ps, 2);
        ps += __shfl_xor_sync(0xffffffffu, ps, 4);
        if (oo == 0) {
            const int slot = (b * 16 + tau) * 16 + kap;
            g_pm[slot * 64 + row] = mt;
            g_pl[slot * 64 + row] = ps;
        }
    }
    __syncthreads();

    // ---- GEMM 2: Y_partial = P V + Pd Ev; fragments stored straight to g_py ----
    {
        const int rt = w >> 2, ct = w & 3;
        HC c; wmma::fill_fragment(c, 0.f);
        #pragma unroll
        for (int k0 = 0; k0 < 4; ++k0) {
            HA pa;
            wmma::load_matrix_sync(pa, &sm.Qh[rt * 16 * LDH + k0 * 16], LDH);
            HBr bv;
            wmma::load_matrix_sync(bv, &sm.Vh[k0 * 16 * LDH + ct * 16], LDH);
            wmma::mma_sync(c, pa, bv, c);
        }
        #pragma unroll
        for (int kk = 0; kk < 5; ++kk) {
            HA pd;   // compressed Pd tile (rt, kk) == original k-tile rt+kk
            wmma::load_matrix_sync(pd, &sm.Pdh[rt * 16 * LDPD + kk * 16], LDPD);
            HBr be;
            wmma::load_matrix_sync(be, &sm.Evh[(rt + kk) * 16 * LDH + ct * 16], LDH);
            wmma::mma_sync(c, pd, be, c);
        }
        const int slot = (b * 16 + tau) * 16 + kap;
        float* yp = g_py + (size_t)slot * 4096;
        wmma::store_matrix_sync(&yp[rt * 16 * 64 + ct * 16], c, 64,
                                wmma::mem_row_major);
    }
}

// ---------------------------------------------------------------------------
// Kernel 3: combine up-to-16 partials + output projection (fused)
// grid = (16, 8), 256 threads
// ---------------------------------------------------------------------------
__global__ __launch_bounds__(256) void combine_proj_kernel(
    const float* __restrict__ W, const float* __restrict__ bias,
    float* __restrict__ out)
{
    __shared__ float Ys[64][65];
    __shared__ float Ws[64][65];

    const int tau = blockIdx.x;
    const int b = blockIdx.y;
    const int nch = tau + 1;
    const int tid = threadIdx.x;

    for (int k = tid; k < 64 * 16; k += 256) {
        int r = k >> 4, c4 = k & 15;
        float4 wv = reinterpret_cast<const float4*>(W + (size_t)r * CC)[c4];
        Ws[r][c4 * 4 + 0] = wv.x; Ws[r][c4 * 4 + 1] = wv.y;
        Ws[r][c4 * 4 + 2] = wv.z; Ws[r][c4 * 4 + 3] = wv.w;
    }

    // combine: 4 threads per row, 16 cols each; fixed-16 unrolled, predicated
    {
        const int row = tid >> 2;
        const int cq = tid & 3;
        const int cb = cq * 16;
        const int slot0 = (b * 16 + tau) * 16;

        float mv[16], lv[16], wgt[16];
        float M = -1e30f;
        #pragma unroll
        for (int k = 0; k < 16; ++k) {
            bool valid = (k < nch);
            mv[k] = valid ? g_pm[(slot0 + k) * 64 + row] : -1e30f;
            lv[k] = valid ? g_pl[(slot0 + k) * 64 + row] : 0.f;
            M = fmaxf(M, mv[k]);
        }
        float L = 0.f;
        #pragma unroll
        for (int k = 0; k < 16; ++k) {
            wgt[k] = __expf(mv[k] - M);
            L += lv[k] * wgt[k];
        }
        float acc[16] = {};
        #pragma unroll
        for (int k = 0; k < 16; ++k) {
            if (k < nch) {
                const float* yp = g_py + (size_t)(slot0 + k) * 4096 + row * 64 + cb;
                float wk = wgt[k];
                #pragma unroll
                for (int q = 0; q < 4; ++q) {
                    float4 v = reinterpret_cast<const float4*>(yp)[q];
                    acc[q * 4 + 0] += wk * v.x; acc[q * 4 + 1] += wk * v.y;
                    acc[q * 4 + 2] += wk * v.z; acc[q * 4 + 3] += wk * v.w;
                }
            }
        }
        float inv = 1.0f / L;
        #pragma unroll
        for (int q = 0; q < 16; ++q)
            Ys[row][cb + q] = acc[q] * inv;
    }
    __syncthreads();

    // projection: 16x16 threads, 4x4 microtile
    {
        const int tx = tid & 15, ty = tid >> 4;
        const int i0 = ty * 4, j0 = tx * 4;
        float acc[4][4] = {};
        #pragma unroll
        for (int c = 0; c < 64; ++c) {
            float xr[4], wr[4];
            #pragma unroll
            for (int i = 0; i < 4; ++i) xr[i] = Ys[i0 + i][c];
            #pragma unroll
            for (int j = 0; j < 4; ++j) wr[j] = Ws[j0 + j][c];
            #pragma unroll
            for (int i = 0; i < 4; ++i)
                #pragma unroll
                for (int j = 0; j < 4; ++j)
                    acc[i][j] = fmaf(xr[i], wr[j], acc[i][j]);
        }
        float* ob = out + ((size_t)b * TT + tau * 64) * CC;
        #pragma unroll
        for (int i = 0; i < 4; ++i)
            #pragma unroll
            for (int j = 0; j < 4; ++j)
                ob[(size_t)(i0 + i) * CC + j0 + j] = acc[i][j] + bias[j0 + j];
    }
}

// ---------------------------------------------------------------------------
extern "C" void kernel_launch(void* const* d_in, const int* in_sizes, int n_in,
                              void* d_out, int out_size)
{
    const float* x     = (const float*)d_in[0];
    const float* Wqkv  = (const float*)d_in[1];
    const float* bqkv  = (const float*)d_in[2];
    const float* embk  = (const float*)d_in[3];
    const float* embv  = (const float*)d_in[4];
    const float* Wproj = (const float*)d_in[5];
    const float* bproj = (const float*)d_in[6];
    float* out = (float*)d_out;

    (void)in_sizes; (void)n_in; (void)out_size;

    cudaFuncSetAttribute(qkv_kernel, cudaFuncAttributeMaxDynamicSharedMemorySize,
                         (int)sizeof(QkvSmem));
    cudaFuncSetAttribute(attn_partial_kernel,
                         cudaFuncAttributeMaxDynamicSharedMemorySize,
                         (int)sizeof(AttnSmem));

    qkv_kernel<<<160, 256, sizeof(QkvSmem)>>>(x, Wqkv, bqkv, embk, embv);
    attn_partial_kernel<<<dim3(136, BB), 512, sizeof(AttnSmem)>>>();
    combine_proj_kernel<<<dim3(16, BB), 256>>>(Wproj, bproj, out);
}

// round 14
// speedup vs baseline: 6.6886x; 1.0773x over previous
#include <cuda_runtime.h>
#include <cuda_fp16.h>
#include <mma.h>
#include <math.h>

using namespace nvcuda;

#define BB 8
#define TT 1024
#define CC 64
#define LDH 72     // half leading dim (mult of 8)
#define LDPD 80    // compressed Pd leading dim (half)
#define LDS1 68    // S1 f32 leading dim (mult of 4)
#define LDS2 80    // compressed S2 f32 leading dim (mult of 4)

// ---- device scratch (zero-initialized at module load) ----
__device__ __align__(16) __half g_qh[BB*TT*CC];
__device__ __align__(16) __half g_kh[BB*TT*CC];
__device__ __align__(16) __half g_vh[BB*TT*CC];
__device__ __align__(16) __half g_ekh[TT*CC];
__device__ __align__(16) __half g_evh[TT*CC];

// split-softmax partials: slot = (b*16 + tau)*16 + kap
__device__ float g_pm[BB*16*16*64];
__device__ float g_pl[BB*16*16*64];
__device__ float g_py[(size_t)BB*16*16*64*64];

// uniform job table: value = tau*16 + kap, one s-tile per job (136 jobs/batch)
__device__ const int c_jt[136] = {
    0,
    16,17,
    32,33,34,
    48,49,50,51,
    64,65,66,67,68,
    80,81,82,83,84,85,
    96,97,98,99,100,101,102,
    112,113,114,115,116,117,118,119,
    128,129,130,131,132,133,134,135,136,
    144,145,146,147,148,149,150,151,152,153,
    160,161,162,163,164,165,166,167,168,169,170,
    176,177,178,179,180,181,182,183,184,185,186,187,
    192,193,194,195,196,197,198,199,200,201,202,203,204,
    208,209,210,211,212,213,214,215,216,217,218,219,220,221,
    224,225,226,227,228,229,230,231,232,233,234,235,236,237,238,
    240,241,242,243,244,245,246,247,248,249,250,251,252,253,254,255
};

typedef wmma::fragment<wmma::matrix_a, 16, 16, 16, __half, wmma::row_major> HA;
typedef wmma::fragment<wmma::matrix_b, 16, 16, 16, __half, wmma::col_major> HBc;
typedef wmma::fragment<wmma::matrix_b, 16, 16, 16, __half, wmma::row_major> HBr;
typedef wmma::fragment<wmma::accumulator, 16, 16, 16, float> HC;

__device__ __forceinline__ void cp16(void* dst, const void* src) {
    unsigned s = (unsigned)__cvta_generic_to_shared(dst);
    asm volatile("cp.async.ca.shared.global [%0], [%1], 16;" :: "r"(s), "l"(src));
}
#define CP_COMMIT() asm volatile("cp.async.commit_group;")
#define CP_WAIT(N)  asm volatile("cp.async.wait_group %0;" :: "n"(N))

// ---------------------------------------------------------------------------
// Kernel 1: qkv = x @ Wqkv^T + bqkv -> g_qh/g_kh/g_vh (half), fp16 wmma.
// grid = (128, 4): y in {0,1,2} = chunk GEMM blocks (64-row tiles, per-chunk W
// slice); y==3, x<32 = emb f32->half conversion. 256 threads (8 warps).
// ---------------------------------------------------------------------------
struct alignas(16) QkvSmem {
    __half Xh[64 * LDH];      // 9216 B
    __half Wh[64 * LDH];      // 9216 B (this chunk's W slice only)
    float  Of[64 * LDS1];     // 17408 B
};

__global__ __launch_bounds__(256, 4) void qkv_kernel(
    const float* __restrict__ x, const float* __restrict__ W,
    const float* __restrict__ bias,
    const float* __restrict__ embk, const float* __restrict__ embv)
{
    const int tid = threadIdx.x;

    if (blockIdx.y == 3) {
        if (blockIdx.x >= 32) return;
        int g = blockIdx.x * 256 + tid;              // 0..8191
        #pragma unroll
        for (int kk = 0; kk < 4; ++kk) {
            int i = g + kk * 8192;                   // 0..32767
            float2 a = reinterpret_cast<const float2*>(embk)[i];
            reinterpret_cast<__half2*>(g_ekh)[i] = __floats2half2_rn(a.x, a.y);
            float2 b = reinterpret_cast<const float2*>(embv)[i];
            reinterpret_cast<__half2*>(g_evh)[i] = __floats2half2_rn(b.x, b.y);
        }
        return;
    }

    extern __shared__ char smem_raw[];
    QkvSmem& sm = *reinterpret_cast<QkvSmem*>(smem_raw);
    const int chunk = blockIdx.y;
    const int row0 = blockIdx.x * 64;
    const int w = tid >> 5;

    // stage x tile and this chunk's W slice (both 64x64 f32 -> half)
    const float* wc = W + (size_t)chunk * 64 * CC;
    #pragma unroll
    for (int kk = 0; kk < 4; ++kk) {
        int k = tid + kk * 256;                      // 0..1023
        int r = k >> 4, c4 = k & 15;
        float4 v = reinterpret_cast<const float4*>(x + (size_t)(row0 + r) * CC)[c4];
        __half2* dx = reinterpret_cast<__half2*>(&sm.Xh[r * LDH + c4 * 4]);
        dx[0] = __floats2half2_rn(v.x, v.y);
        dx[1] = __floats2half2_rn(v.z, v.w);
        float4 wv = reinterpret_cast<const float4*>(wc + (size_t)r * CC)[c4];
        __half2* dw = reinterpret_cast<__half2*>(&sm.Wh[r * LDH + c4 * 4]);
        dw[0] = __floats2half2_rn(wv.x, wv.y);
        dw[1] = __floats2half2_rn(wv.z, wv.w);
    }
    __syncthreads();

    // 16 tiles (4 rt x 4 ct): warp w does rt = w&3, ct = 2*(w>>2) + {0,1}.
    // A fragment loaded once per k-step, shared by both tiles.
    {
        const int rt = w & 3;
        const int ct0 = (w >> 2) * 2;
        HC c0, c1;
        wmma::fill_fragment(c0, 0.f);
        wmma::fill_fragment(c1, 0.f);
        #pragma unroll
        for (int k0 = 0; k0 < 4; ++k0) {
            HA ax;
            wmma::load_matrix_sync(ax, &sm.Xh[rt * 16 * LDH + k0 * 16], LDH);
            HBc bw;
            wmma::load_matrix_sync(bw, &sm.Wh[ct0 * 16 * LDH + k0 * 16], LDH);
            wmma::mma_sync(c0, ax, bw, c0);
            wmma::load_matrix_sync(bw, &sm.Wh[(ct0 + 1) * 16 * LDH + k0 * 16], LDH);
            wmma::mma_sync(c1, ax, bw, c1);
        }
        wmma::store_matrix_sync(&sm.Of[rt * 16 * LDS1 + ct0 * 16], c0, LDS1,
                                wmma::mem_row_major);
        wmma::store_matrix_sync(&sm.Of[rt * 16 * LDS1 + (ct0 + 1) * 16], c1, LDS1,
                                wmma::mem_row_major);
    }
    __syncthreads();

    // uniform output pass: bias add + convert, coalesced half2 stores
    __half* outp = (chunk == 0) ? g_qh : (chunk == 1) ? g_kh : g_vh;
    const float* bc = bias + chunk * 64;
    #pragma unroll
    for (int kk = 0; kk < 8; ++kk) {
        int k = tid + kk * 256;                      // 0..2047
        int r = k >> 5, c2 = (k & 31) * 2;
        float v0 = sm.Of[r * LDS1 + c2]     + bc[c2];
        float v1 = sm.Of[r * LDS1 + c2 + 1] + bc[c2 + 1];
        *reinterpret_cast<__half2*>(&outp[(size_t)(row0 + r) * CC + c2]) =
            __floats2half2_rn(v0, v1);
    }
}

// ---------------------------------------------------------------------------
// Kernel 2: single-s-tile partial attention job, fp16 wmma, occupancy 2.
// grid = (136, 8), 512 threads (16 warps). Smem ~113 KB. cp.async staging.
// ---------------------------------------------------------------------------
struct alignas(16) AttnSmem {
    __half Qh[64 * LDH];      // 9216  (aliased as Ph after GEMM1)
    __half Kh[64 * LDH];      // 9216
    __half Vh[64 * LDH];      // 9216
    __half Ekh[128 * LDH];    // 18432
    __half Evh[128 * LDH];    // 18432
    __half Pdh[64 * LDPD];    // 10240 (band-compressed Pd)
    float  S1f[64 * LDS1];    // 17408
    float  S2f[64 * LDS2];    // 20480 (band-compressed S2)
};  // total 112640 B

__global__ __launch_bounds__(512, 2) void attn_partial_kernel()
{
    extern __shared__ char smem_raw[];
    AttnSmem& sm = *reinterpret_cast<AttnSmem*>(smem_raw);

    const int b = blockIdx.y;
    const int job = c_jt[blockIdx.x];
    const int tau = job >> 4;
    const int kap = job & 15;
    const int t0 = tau * 64;
    const int s0 = kap * 64;
    const int D = t0 - s0;                 // >= 0

    const int tid = threadIdx.x;
    const int w = tid >> 5;

    // softmax mapping: 8 threads per row, 8 cols each
    const int row = tid >> 3;
    const int oo = tid & 7;
    const int jb = oo * 8;
    const int rr = row & 15;               // row within its 16-row tile

    // ---- stage via cp.async: group A = Q,K,Ek (GEMM1 needs), group B = V,Ev ----
    {
        const uint4* qg = reinterpret_cast<const uint4*>(g_qh + ((size_t)b * TT + t0) * CC);
        const uint4* kg = reinterpret_cast<const uint4*>(g_kh + ((size_t)b * TT + s0) * CC);
        const uint4* vg = reinterpret_cast<const uint4*>(g_vh + ((size_t)b * TT + s0) * CC);
        uint4* qs = reinterpret_cast<uint4*>(sm.Qh);
        uint4* ks = reinterpret_cast<uint4*>(sm.Kh);
        uint4* vs = reinterpret_cast<uint4*>(sm.Vh);
        const uint4* eg = reinterpret_cast<const uint4*>(g_ekh);
        const uint4* eg2 = reinterpret_cast<const uint4*>(g_evh);
        uint4* es = reinterpret_cast<uint4*>(sm.Ekh);
        uint4* es2 = reinterpret_cast<uint4*>(sm.Evh);

        const int r = tid >> 3, c = tid & 7;         // 512 items each
        const int base = D - 63;
        int e0 = base + r;          e0 = (e0 < 0) ? 0 : (e0 > TT - 1 ? TT - 1 : e0);
        int e1 = base + r + 64;     e1 = (e1 < 0) ? 0 : (e1 > TT - 1 ? TT - 1 : e1);

        // group A
        cp16(&qs[r * 9 + c], &qg[r * 8 + c]);
        cp16(&ks[r * 9 + c], &kg[r * 8 + c]);
        cp16(&es[r * 9 + c], &eg[e0 * 8 + c]);
        cp16(&es[(r + 64) * 9 + c], &eg[e1 * 8 + c]);
        CP_COMMIT();
        // group B
        cp16(&vs[r * 9 + c], &vg[r * 8 + c]);
        cp16(&es2[r * 9 + c], &eg2[e0 * 8 + c]);
        cp16(&es2[(r + 64) * 9 + c], &eg2[e1 * 8 + c]);
        CP_COMMIT();
    }
    CP_WAIT(1);          // Q, K, Ek landed; V/Ev may still be in flight
    __syncthreads();

    // ---- GEMM 1: S1 (4 tiles/rt) + S2 band (5 tiles/rt); A loaded per k-step ----
    {
        const int rt = w >> 2;
        const int q = ((w & 3) + rt) & 3;            // rotate imbalance across SMSPs
        const int nt = (q == 0) ? 3 : 2;             // tiles t = q, q+4, (q+8)

        const __half* bsrc[3];
        float* dstp[3];
        unsigned ldd[3];
        #pragma unroll
        for (int i = 0; i < 3; ++i) {
            int t = q + 4 * i;
            if (t < 4) {
                bsrc[i] = &sm.Kh[t * 16 * LDH];
                dstp[i] = &sm.S1f[rt * 16 * LDS1 + t * 16];
                ldd[i] = LDS1;
            } else if (t < 9) {
                int ce = rt + (t - 4);               // band col-tile in [rt, rt+4]
                bsrc[i] = &sm.Ekh[ce * 16 * LDH];
                dstp[i] = &sm.S2f[rt * 16 * LDS2 + (t - 4) * 16];
                ldd[i] = LDS2;
            } else {
                bsrc[i] = &sm.Kh[0];
                dstp[i] = &sm.S1f[0];
                ldd[i] = LDS1;
            }
        }

        HC c0, c1, c2;
        wmma::fill_fragment(c0, 0.f);
        wmma::fill_fragment(c1, 0.f);
        wmma::fill_fragment(c2, 0.f);
        #pragma unroll
        for (int k0 = 0; k0 < 4; ++k0) {
            HA aq;
            wmma::load_matrix_sync(aq, &sm.Qh[rt * 16 * LDH + k0 * 16], LDH);
            HBc bf;
            wmma::load_matrix_sync(bf, bsrc[0] + k0 * 16, LDH);
            wmma::mma_sync(c0, aq, bf, c0);
            wmma::load_matrix_sync(bf, bsrc[1] + k0 * 16, LDH);
            wmma::mma_sync(c1, aq, bf, c1);
            if (nt == 3) {
                wmma::load_matrix_sync(bf, bsrc[2] + k0 * 16, LDH);
                wmma::mma_sync(c2, aq, bf, c2);
            }
        }
        wmma::store_matrix_sync(dstp[0], c0, ldd[0], wmma::mem_row_major);
        wmma::store_matrix_sync(dstp[1], c1, ldd[1], wmma::mem_row_major);
        if (nt == 3)
            wmma::store_matrix_sync(dstp[2], c2, ldd[2], wmma::mem_row_major);
    }
    __syncthreads();

    // ---- softmax (single s-tile): write P (into Qh alias) + compressed Pd ----
    {
        float sv[8];
        float mt = -1e30f;
        #pragma unroll
        for (int jj = 0; jj < 8; ++jj) {
            int j = jb + jj;
            int c2 = rr + 63 - j;                    // compressed S2 col
            float s = (sm.S1f[row * LDS1 + j] + sm.S2f[row * LDS2 + c2]) * 0.125f;
            if (j > D + row) s = -1e30f;             // causal mask
            sv[jj] = s;
            mt = fmaxf(mt, s);
        }
        mt = fmaxf(mt, __shfl_xor_sync(0xffffffffu, mt, 1));
        mt = fmaxf(mt, __shfl_xor_sync(0xffffffffu, mt, 2));
        mt = fmaxf(mt, __shfl_xor_sync(0xffffffffu, mt, 4));
        float ps = 0.f;
        #pragma unroll
        for (int jj = 0; jj < 8; ++jj) {
            int j = jb + jj;
            float p = __expf(sv[jj] - mt);
            ps += p;
            sm.Qh[row * LDH + j] = __float2half(p);               // P (aliases Qh)
            sm.Pdh[row * LDPD + (rr + 63 - j)] = __float2half(p); // band [rr, rr+63]
        }
        // zero band complement: cols (rr+64+k) % 80 for k in [0,16), 2 per thread
        #pragma unroll
        for (int kz = 0; kz < 2; ++kz) {
            int z = (rr + 64 + oo * 2 + kz) % 80;
            sm.Pdh[row * LDPD + z] = __float2half(0.f);
        }
        ps += __shfl_xor_sync(0xffffffffu, ps, 1);
        ps += __shfl_xor_sync(0xffffffffu, ps, 2);
        ps += __shfl_xor_sync(0xffffffffu, ps, 4);
        if (oo == 0) {
            const int slot = (b * 16 + tau) * 16 + kap;
            g_pm[slot * 64 + row] = mt;
            g_pl[slot * 64 + row] = ps;
        }
    }
    CP_WAIT(0);          // V, Ev landed
    __syncthreads();

    // ---- GEMM 2: Y_partial = P V + Pd Ev; fragments stored straight to g_py ----
    {
        const int rt = w >> 2, ct = w & 3;
        HC c; wmma::fill_fragment(c, 0.f);
        #pragma unroll
        for (int k0 = 0; k0 < 4; ++k0) {
            HA pa;
            wmma::load_matrix_sync(pa, &sm.Qh[rt * 16 * LDH + k0 * 16], LDH);
            HBr bv;
            wmma::load_matrix_sync(bv, &sm.Vh[k0 * 16 * LDH + ct * 16], LDH);
            wmma::mma_sync(c, pa, bv, c);
        }
        #pragma unroll
        for (int kk = 0; kk < 5; ++kk) {
            HA pd;   // compressed Pd tile (rt, kk) == original k-tile rt+kk
            wmma::load_matrix_sync(pd, &sm.Pdh[rt * 16 * LDPD + kk * 16], LDPD);
            HBr be;
            wmma::load_matrix_sync(be, &sm.Evh[(rt + kk) * 16 * LDH + ct * 16], LDH);
            wmma::mma_sync(c, pd, be, c);
        }
        const int slot = (b * 16 + tau) * 16 + kap;
        float* yp = g_py + (size_t)slot * 4096;
        wmma::store_matrix_sync(&yp[rt * 16 * 64 + ct * 16], c, 64,
                                wmma::mem_row_major);
    }
}

// ---------------------------------------------------------------------------
// Kernel 3: combine up-to-16 partials + output projection (fused)
// grid = (16, 8), 256 threads
// ---------------------------------------------------------------------------
__global__ __launch_bounds__(256) void combine_proj_kernel(
    const float* __restrict__ W, const float* __restrict__ bias,
    float* __restrict__ out)
{
    __shared__ float Ys[64][65];
    __shared__ float Ws[64][65];

    const int tau = blockIdx.x;
    const int b = blockIdx.y;
    const int nch = tau + 1;
    const int tid = threadIdx.x;

    for (int k = tid; k < 64 * 16; k += 256) {
        int r = k >> 4, c4 = k & 15;
        float4 wv = reinterpret_cast<const float4*>(W + (size_t)r * CC)[c4];
        Ws[r][c4 * 4 + 0] = wv.x; Ws[r][c4 * 4 + 1] = wv.y;
        Ws[r][c4 * 4 + 2] = wv.z; Ws[r][c4 * 4 + 3] = wv.w;
    }

    // combine: 4 threads per row, 16 cols each
    {
        const int row = tid >> 2;
        const int cq = tid & 3;
        const int cb = cq * 16;
        const int slot0 = (b * 16 + tau) * 16;

        float mv[16], lv[16], wgt[16];
        float M = -1e30f;
        #pragma unroll
        for (int k = 0; k < 16; ++k) {
            bool valid = (k < nch);
            mv[k] = valid ? g_pm[(slot0 + k) * 64 + row] : -1e30f;
            lv[k] = valid ? g_pl[(slot0 + k) * 64 + row] : 0.f;
            M = fmaxf(M, mv[k]);
        }
        float L = 0.f;
        #pragma unroll
        for (int k = 0; k < 16; ++k) {
            wgt[k] = __expf(mv[k] - M);
            L += lv[k] * wgt[k];
        }
        float acc[16] = {};
        #pragma unroll
        for (int k = 0; k < 16; ++k) {
            if (k < nch) {
                const float* yp = g_py + (size_t)(slot0 + k) * 4096 + row * 64 + cb;
                float wk = wgt[k];
                #pragma unroll
                for (int q = 0; q < 4; ++q) {
                    float4 v = reinterpret_cast<const float4*>(yp)[q];
                    acc[q * 4 + 0] += wk * v.x; acc[q * 4 + 1] += wk * v.y;
                    acc[q * 4 + 2] += wk * v.z; acc[q * 4 + 3] += wk * v.w;
                }
            }
        }
        float inv = 1.0f / L;
        #pragma unroll
        for (int q = 0; q < 16; ++q)
            Ys[row][cb + q] = acc[q] * inv;
    }
    __syncthreads();

    // projection: 16x16 threads, 4x4 microtile
    {
        const int tx = tid & 15, ty = tid >> 4;
        const int i0 = ty * 4, j0 = tx * 4;
        float acc[4][4] = {};
        #pragma unroll
        for (int c = 0; c < 64; ++c) {
            float xr[4], wr[4];
            #pragma unroll
            for (int i = 0; i < 4; ++i) xr[i] = Ys[i0 + i][c];
            #pragma unroll
            for (int j = 0; j < 4; ++j) wr[j] = Ws[j0 + j][c];
            #pragma unroll
            for (int i = 0; i < 4; ++i)
                #pragma unroll
                for (int j = 0; j < 4; ++j)
                    acc[i][j] = fmaf(xr[i], wr[j], acc[i][j]);
        }
        float* ob = out + ((size_t)b * TT + tau * 64) * CC;
        #pragma unroll
        for (int i = 0; i < 4; ++i)
            #pragma unroll
            for (int j = 0; j < 4; ++j)
                ob[(size_t)(i0 + i) * CC + j0 + j] = acc[i][j] + bias[j0 + j];
    }
}

// ---------------------------------------------------------------------------
extern "C" void kernel_launch(void* const* d_in, const int* in_sizes, int n_in,
                              void* d_out, int out_size)
{
    const float* x     = (const float*)d_in[0];
    const float* Wqkv  = (const float*)d_in[1];
    const float* bqkv  = (const float*)d_in[2];
    const float* embk  = (const float*)d_in[3];
    const float* embv  = (const float*)d_in[4];
    const float* Wproj = (const float*)d_in[5];
    const float* bproj = (const float*)d_in[6];
    float* out = (float*)d_out;

    (void)in_sizes; (void)n_in; (void)out_size;

    cudaFuncSetAttribute(qkv_kernel, cudaFuncAttributeMaxDynamicSharedMemorySize,
                         (int)sizeof(QkvSmem));
    cudaFuncSetAttribute(attn_partial_kernel,
                         cudaFuncAttributeMaxDynamicSharedMemorySize,
                         (int)sizeof(AttnSmem));

    qkv_kernel<<<dim3(128, 4), 256, sizeof(QkvSmem)>>>(x, Wqkv, bqkv, embk, embv);
    attn_partial_kernel<<<dim3(136, BB), 512, sizeof(AttnSmem)>>>();
    combine_proj_kernel<<<dim3(16, BB), 256>>>(Wproj, bproj, out);
}